// round 2
// baseline (speedup 1.0000x reference)
#include <cuda_runtime.h>
#include <cstdint>

#define NN 12288
#define EE 393216
#define HH 256
#define DOUTC 128

// ---------------- scratch (static device globals; no allocation) -------------
static __device__ unsigned g_bitmap[((size_t)NN * NN) / 32];     // 18.9 MB dedup bitmap
static __device__ int      g_deg[NN];
static __device__ int      g_cursor[NN];
static __device__ int      g_rowptr[NN + 1];
static __device__ float    g_invdeg[NN];
static __device__ int      g_ds[EE];
static __device__ int      g_dd[EE];
static __device__ int      g_col[2 * EE];
static __device__ int      g_ndedup;
static __device__ int      g_is64;
static __device__ float    g_bufA[(size_t)NN * HH];
static __device__ float    g_bufB[(size_t)NN * HH];
static __device__ float    g_bufC[(size_t)NN * HH];

// ---------------- setup kernels ---------------------------------------------
__global__ void k_init(const int* __restrict__ p32) {
    int i = blockIdx.x * 256 + threadIdx.x;
    if (i < NN) { g_deg[i] = 0; g_cursor[i] = 0; }
    if (blockIdx.x == 0) {
        __shared__ int anynz;
        if (threadIdx.x == 0) { anynz = 0; g_ndedup = 0; }
        __syncthreads();
        // int64 little-endian high words sit at odd int32 slots; all-zero over
        // 256 samples => int64. Genuine random int32 edge data can't do this.
        if (p32[2 * threadIdx.x + 1] != 0) atomicOr(&anynz, 1);
        __syncthreads();
        if (threadIdx.x == 0) g_is64 = anynz ? 0 : 1;
    }
}

__global__ void k_dedup(const int* __restrict__ p32) {
    int e = blockIdx.x * 256 + threadIdx.x;
    if (e >= EE) return;
    int s, d;
    if (g_is64) { s = p32[2 * e]; d = p32[2 * (EE + e)]; }
    else        { s = p32[e];     d = p32[EE + e]; }
    size_t bi = (size_t)s * NN + d;
    unsigned m = 1u << (bi & 31);
    unsigned old = atomicOr(&g_bitmap[bi >> 5], m);
    if (!(old & m)) {
        int idx = atomicAdd(&g_ndedup, 1);
        g_ds[idx] = s; g_dd[idx] = d;
        atomicAdd(&g_deg[s], 1);
        atomicAdd(&g_deg[d], 1);
    }
}

__global__ void k_scan() {   // 1 block, 256 threads; NN = 256 * 48
    __shared__ int partial[256];
    const int CH = NN / 256;
    int t = threadIdx.x;
    int base = t * CH;
    int s = 0;
    for (int k = 0; k < CH; k++) s += g_deg[base + k];
    partial[t] = s;
    __syncthreads();
    if (t == 0) {
        int acc = 0;
        for (int i = 0; i < 256; i++) { int v = partial[i]; partial[i] = acc; acc += v; }
    }
    __syncthreads();
    int run = partial[t];
    for (int k = 0; k < CH; k++) {
        int dg = g_deg[base + k];
        g_rowptr[base + k] = run;
        g_invdeg[base + k] = 1.0f / ((float)dg + 1e-8f);
        run += dg;
    }
    if (t == 255) g_rowptr[NN] = run;
}

__global__ void k_fill() {
    int i = blockIdx.x * 256 + threadIdx.x;
    if (i >= g_ndedup) return;
    int s = g_ds[i], d = g_dd[i];
    int p = g_rowptr[s] + atomicAdd(&g_cursor[s], 1);
    g_col[p] = d;
    int q = g_rowptr[d] + atomicAdd(&g_cursor[d], 1);
    g_col[q] = s;
}

// ---------------- SpMM: y = x + invdeg[row] * sum_{j in nbr(row)} x[j] ------
__global__ void k_spmm(const float* __restrict__ x, float* __restrict__ y) {
    int row = blockIdx.x;
    int t = threadIdx.x;                       // column 0..255
    int beg = g_rowptr[row], end = g_rowptr[row + 1];
    __shared__ int cs[256];
    float acc = 0.f;
    for (int c0 = beg; c0 < end; c0 += 256) {
        int n = min(256, end - c0);
        __syncthreads();
        if (t < n) cs[t] = g_col[c0 + t];
        __syncthreads();
        int k = 0;
        for (; k + 4 <= n; k += 4) {
            float v0 = x[(size_t)cs[k + 0] * HH + t];
            float v1 = x[(size_t)cs[k + 1] * HH + t];
            float v2 = x[(size_t)cs[k + 2] * HH + t];
            float v3 = x[(size_t)cs[k + 3] * HH + t];
            acc += v0 + v1 + v2 + v3;
        }
        for (; k < n; k++) acc += x[(size_t)cs[k] * HH + t];
    }
    size_t o = (size_t)row * HH + t;
    y[o] = x[o] + g_invdeg[row] * acc;
}

// ---------------- tiled SGEMM: C[NxM] = act(A[NxK] @ W[MxK]^T + bias) -------
// 128x128 tile, 256 threads, 8x8 per thread, BK=8, float4 paths, +4 smem pad.
template <int RELU>
__global__ void __launch_bounds__(256)
k_gemm(const float* __restrict__ A, const float* __restrict__ W,
       const float* __restrict__ bias, float* __restrict__ C,
       int K, int M, int ldc) {
    __shared__ float As[8][132];
    __shared__ float Bs[8][132];
    const int t = threadIdx.x;
    const int lr = t >> 1;
    const int lk = (t & 1) * 4;
    const int tx = t & 15, ty = t >> 4;
    const int row0 = blockIdx.x * 128;
    const int col0 = blockIdx.y * 128;

    float acc[8][8];
#pragma unroll
    for (int i = 0; i < 8; i++)
#pragma unroll
        for (int j = 0; j < 8; j++) acc[i][j] = 0.f;

    const float* aptr = A + (size_t)(row0 + lr) * K + lk;
    const int m = col0 + lr;
    const bool wok = (m < M);
    const float* wptr = W + (size_t)(wok ? m : 0) * K + lk;

    for (int k0 = 0; k0 < K; k0 += 8) {
        float4 av = *(const float4*)(aptr + k0);
        float4 wv = make_float4(0.f, 0.f, 0.f, 0.f);
        if (wok) wv = *(const float4*)(wptr + k0);
        As[lk + 0][lr] = av.x; As[lk + 1][lr] = av.y;
        As[lk + 2][lr] = av.z; As[lk + 3][lr] = av.w;
        Bs[lk + 0][lr] = wv.x; Bs[lk + 1][lr] = wv.y;
        Bs[lk + 2][lr] = wv.z; Bs[lk + 3][lr] = wv.w;
        __syncthreads();
#pragma unroll
        for (int k = 0; k < 8; k++) {
            float a[8], b[8];
#pragma unroll
            for (int i = 0; i < 8; i++) a[i] = As[k][ty * 8 + i];
#pragma unroll
            for (int j = 0; j < 8; j++) b[j] = Bs[k][tx * 8 + j];
#pragma unroll
            for (int i = 0; i < 8; i++)
#pragma unroll
                for (int j = 0; j < 8; j++) acc[i][j] += a[i] * b[j];
        }
        __syncthreads();
    }

#pragma unroll
    for (int i = 0; i < 8; i++) {
        int r = row0 + ty * 8 + i;
#pragma unroll
        for (int j = 0; j < 8; j++) {
            int c = col0 + tx * 8 + j;
            if (c < M) {
                float v = acc[i][j] + bias[c];
                if (RELU) v = fmaxf(v, 0.f);
                C[(size_t)r * ldc + c] = v;
            }
        }
    }
}

// ---------------- tiny GEMM: out[Nx8] = X[Nx64] @ W[8x64]^T + b -------------
__global__ void k_gemm8(const float* __restrict__ X, const float* __restrict__ W,
                        const float* __restrict__ b, float* __restrict__ out) {
    __shared__ float ws[8][64];
    __shared__ float bs[8];
    int t = threadIdx.x;
    for (int i = t; i < 512; i += 256) ws[i >> 6][i & 63] = W[i];
    if (t < 8) bs[t] = b[t];
    __syncthreads();
    int r = blockIdx.x * 256 + t;
    float acc[8];
#pragma unroll
    for (int j = 0; j < 8; j++) acc[j] = bs[j];
    const float* xr = X + (size_t)r * 64;
#pragma unroll
    for (int k = 0; k < 64; k++) {
        float xv = xr[k];
#pragma unroll
        for (int j = 0; j < 8; j++) acc[j] += xv * ws[j][k];
    }
#pragma unroll
    for (int j = 0; j < 8; j++) out[(size_t)r * 8 + j] = acc[j];
}

// ---------------- column mean of ne [N x 128] -> gf [128] -------------------
__global__ void k_zero_gf(float* gf) { gf[threadIdx.x] = 0.f; }

__global__ void k_colsum(const float* __restrict__ ne, float* __restrict__ gf) {
    int col = threadIdx.x;                    // 128
    int r0 = blockIdx.x * 128;
    float s = 0.f;
    for (int r = 0; r < 128; r++) s += ne[(size_t)(r0 + r) * DOUTC + col];
    atomicAdd(&gf[col], s);
}

__global__ void k_scale_gf(float* gf) { gf[threadIdx.x] *= (1.0f / NN); }

// ---------------- launch ----------------------------------------------------
extern "C" void kernel_launch(void* const* d_in, const int* in_sizes, int n_in,
                              void* d_out, int out_size) {
    const float* X      = (const float*)d_in[0];
    const int*   EIDX   = (const int*)d_in[1];
    const float* enc_w1 = (const float*)d_in[2];
    const float* enc_b1 = (const float*)d_in[3];
    const float* enc_w2 = (const float*)d_in[4];
    const float* enc_b2 = (const float*)d_in[5];
    const float* gin_w  = (const float*)d_in[6];
    const float* gin_b  = (const float*)d_in[7];
    const float* gl_w   = (const float*)d_in[8];
    const float* gl_b   = (const float*)d_in[9];
    const float* gout_w = (const float*)d_in[10];
    const float* gout_b = (const float*)d_in[11];
    const float* proj_w = (const float*)d_in[12];
    const float* proj_b = (const float*)d_in[13];
    const float* hc_w1  = (const float*)d_in[14];
    const float* hc_b1  = (const float*)d_in[15];
    const float* hc_w2  = (const float*)d_in[16];
    const float* hc_b2  = (const float*)d_in[17];

    float* out = (float*)d_out;
    float* ne  = out;                               // [N, 128]
    float* hl  = out + (size_t)NN * DOUTC;          // [N, 8]
    float* gf  = hl + (size_t)NN * 8;               // [128]

    // Resolve scratch addresses once (pure address lookups, deterministic).
    static float* bA = nullptr;
    static float* bB = nullptr;
    static float* bC = nullptr;
    static void*  bmap = nullptr;
    if (!bA) {
        cudaGetSymbolAddress((void**)&bA, g_bufA);
        cudaGetSymbolAddress((void**)&bB, g_bufB);
        cudaGetSymbolAddress((void**)&bC, g_bufC);
        cudaGetSymbolAddress(&bmap, g_bitmap);
    }

    const int EB = EE / 256;                        // 1536

    // graph build
    k_init<<<NN / 256, 256>>>(EIDX);
    cudaMemsetAsync(bmap, 0, ((size_t)NN * NN) / 8);
    k_dedup<<<EB, 256>>>(EIDX);
    k_scan<<<1, 256>>>();
    k_fill<<<EB, 256>>>();

    dim3 g2(NN / 128, 2), g1(NN / 128, 1);

    // node encoder
    k_gemm<1><<<g2, 256>>>(X,  enc_w1, enc_b1, bA, 256, 256, 256);
    k_gemm<0><<<g2, 256>>>(bA, enc_w2, enc_b2, bB, 256, 256, 256);
    // gnn input proj
    k_gemm<1><<<g2, 256>>>(bB, gin_w, gin_b, bA, 256, 256, 256);
    // 3 message-passing layers
    for (int i = 0; i < 3; i++) {
        k_spmm<<<NN, 256>>>(bA, bC);
        k_gemm<1><<<g2, 256>>>(bC, gl_w + (size_t)i * HH * HH, gl_b + (size_t)i * HH,
                               bA, 256, 256, 256);
    }
    // gnn output proj
    k_gemm<0><<<g2, 256>>>(bA, gout_w, gout_b, bB, 256, 256, 256);
    // hierarchy output proj -> node_embeddings (written straight into d_out)
    k_gemm<1><<<g1, 256>>>(bB, proj_w, proj_b, ne, 256, 128, 128);
    // classifier
    k_gemm<1><<<g1, 256>>>(ne, hc_w1, hc_b1, bC, 128, 64, 64);
    k_gemm8<<<NN / 256, 256>>>(bC, hc_w2, hc_b2, hl);
    // global mean
    k_zero_gf<<<1, 128>>>(gf);
    k_colsum<<<NN / 128, 128>>>(ne, gf);
    k_scale_gf<<<1, 128>>>(gf);
}

// round 3
// speedup vs baseline: 1.5876x; 1.5876x over previous
#include <cuda_runtime.h>
#include <cuda_bf16.h>
#include <cstdint>

#define NN 12288
#define EE 393216
#define HH 256
#define DOUTC 128

// ---------------- scratch (static device globals; no allocation) -------------
static __device__ unsigned g_bitmap[((size_t)NN * NN) / 32];     // 18.9 MB dedup bitmap
static __device__ int      g_deg[NN];
static __device__ int      g_cursor[NN];
static __device__ int      g_rowptr[NN + 1];
static __device__ float    g_invdeg[NN];
static __device__ int      g_ds[EE];
static __device__ int      g_dd[EE];
static __device__ int      g_col[2 * EE];
static __device__ int      g_ndedup;
static __device__ int      g_is64;
static __device__ float    g_bufA[(size_t)NN * HH];              // fp32 activations (spmm in)
static __device__ float    g_bufC[(size_t)NN * HH];              // fp32 scratch (hc1 out)
// bf16 split activation ping-pong
static __device__ __nv_bfloat16 g_Phi[(size_t)NN * HH];
static __device__ __nv_bfloat16 g_Plo[(size_t)NN * HH];
static __device__ __nv_bfloat16 g_Qhi[(size_t)NN * HH];
static __device__ __nv_bfloat16 g_Qlo[(size_t)NN * HH];
// bf16 split weights (concatenated)
#define OFF_ENC1 0
#define OFF_ENC2 65536
#define OFF_GIN  131072
#define OFF_GL   196608
#define OFF_GOUT 393216
#define OFF_PROJ 458752
#define OFF_HC1  491520
#define WTOT     499712
static __device__ __nv_bfloat16 g_Whi[WTOT];
static __device__ __nv_bfloat16 g_Wlo[WTOT];

// ---------------- setup kernels ---------------------------------------------
__global__ void k_init(const int* __restrict__ p32) {
    int i = blockIdx.x * 256 + threadIdx.x;
    if (i < NN) { g_deg[i] = 0; g_cursor[i] = 0; }
    if (blockIdx.x == 0) {
        __shared__ int anynz;
        if (threadIdx.x == 0) { anynz = 0; g_ndedup = 0; }
        __syncthreads();
        if (p32[2 * threadIdx.x + 1] != 0) atomicOr(&anynz, 1);
        __syncthreads();
        if (threadIdx.x == 0) g_is64 = anynz ? 0 : 1;
    }
}

__global__ void k_dedup(const int* __restrict__ p32) {
    int e = blockIdx.x * 256 + threadIdx.x;
    if (e >= EE) return;
    int s, d;
    if (g_is64) { s = p32[2 * e]; d = p32[2 * (EE + e)]; }
    else        { s = p32[e];     d = p32[EE + e]; }
    size_t bi = (size_t)s * NN + d;
    unsigned m = 1u << (bi & 31);
    unsigned old = atomicOr(&g_bitmap[bi >> 5], m);
    if (!(old & m)) {
        int idx = atomicAdd(&g_ndedup, 1);
        g_ds[idx] = s; g_dd[idx] = d;
        atomicAdd(&g_deg[s], 1);
        atomicAdd(&g_deg[d], 1);
    }
}

__global__ void k_scan() {   // 1 block, 256 threads; NN = 256 * 48
    __shared__ int partial[256];
    const int CH = NN / 256;
    int t = threadIdx.x;
    int base = t * CH;
    int s = 0;
    for (int k = 0; k < CH; k++) s += g_deg[base + k];
    partial[t] = s;
    __syncthreads();
    if (t == 0) {
        int acc = 0;
        for (int i = 0; i < 256; i++) { int v = partial[i]; partial[i] = acc; acc += v; }
    }
    __syncthreads();
    int run = partial[t];
    for (int k = 0; k < CH; k++) {
        int dg = g_deg[base + k];
        g_rowptr[base + k] = run;
        g_invdeg[base + k] = 1.0f / ((float)dg + 1e-8f);
        run += dg;
    }
    if (t == 255) g_rowptr[NN] = run;
}

__global__ void k_fill() {
    int i = blockIdx.x * 256 + threadIdx.x;
    if (i >= g_ndedup) return;
    int s = g_ds[i], d = g_dd[i];
    int p = g_rowptr[s] + atomicAdd(&g_cursor[s], 1);
    g_col[p] = d;
    int q = g_rowptr[d] + atomicAdd(&g_cursor[d], 1);
    g_col[q] = s;
}

// ---------------- fp32 -> bf16 hi/lo split ----------------------------------
__device__ __forceinline__ void split1(float v, __nv_bfloat16& h, __nv_bfloat16& l) {
    h = __float2bfloat16_rn(v);
    l = __float2bfloat16_rn(v - __bfloat162float(h));
}

__global__ void k_split(const float* __restrict__ src,
                        __nv_bfloat16* __restrict__ hi,
                        __nv_bfloat16* __restrict__ lo) {
    int i = (blockIdx.x * 256 + threadIdx.x) * 4;
    float4 v = *(const float4*)(src + i);
    __nv_bfloat16 h0, h1, h2, h3, l0, l1, l2, l3;
    split1(v.x, h0, l0); split1(v.y, h1, l1);
    split1(v.z, h2, l2); split1(v.w, h3, l3);
    *(__nv_bfloat162*)(hi + i)     = __nv_bfloat162(h0, h1);
    *(__nv_bfloat162*)(hi + i + 2) = __nv_bfloat162(h2, h3);
    *(__nv_bfloat162*)(lo + i)     = __nv_bfloat162(l0, l1);
    *(__nv_bfloat162*)(lo + i + 2) = __nv_bfloat162(l2, l3);
}

// ---------------- SpMM: y = x + invdeg[row]*sum x[j]; emits bf16 hi/lo ------
__global__ void k_spmm(const float* __restrict__ x,
                       __nv_bfloat16* __restrict__ yh,
                       __nv_bfloat16* __restrict__ yl) {
    int row = blockIdx.x;
    int t = threadIdx.x;                       // column 0..255
    int beg = g_rowptr[row], end = g_rowptr[row + 1];
    __shared__ int cs[256];
    float acc = 0.f;
    for (int c0 = beg; c0 < end; c0 += 256) {
        int n = min(256, end - c0);
        __syncthreads();
        if (t < n) cs[t] = g_col[c0 + t];
        __syncthreads();
        int k = 0;
        for (; k + 4 <= n; k += 4) {
            float v0 = x[(size_t)cs[k + 0] * HH + t];
            float v1 = x[(size_t)cs[k + 1] * HH + t];
            float v2 = x[(size_t)cs[k + 2] * HH + t];
            float v3 = x[(size_t)cs[k + 3] * HH + t];
            acc += v0 + v1 + v2 + v3;
        }
        for (; k < n; k++) acc += x[(size_t)cs[k] * HH + t];
    }
    size_t o = (size_t)row * HH + t;
    float v = x[o] + g_invdeg[row] * acc;
    __nv_bfloat16 h, l; split1(v, h, l);
    yh[o] = h; yl[o] = l;
}

// ---------------- bf16x3 tensor-core GEMM -----------------------------------
// C[N x M] = act(A[N x K] @ W[M x K]^T + bias), A/W pre-split into bf16 hi/lo.
// CTA tile 128x64, 8 warps of 32x32, K-tile 16, cp.async double buffer.
#define BM 128
#define BN 64
#define KT 16

__device__ __forceinline__ void cpa16(uint32_t s, const void* g) {
    asm volatile("cp.async.cg.shared.global [%0], [%1], 16;\n" :: "r"(s), "l"(g));
}
#define CP_COMMIT() asm volatile("cp.async.commit_group;\n" ::: "memory")
#define CP_WAIT0()  asm volatile("cp.async.wait_group 0;\n" ::: "memory")

#define MMA_B16(d, a, b)                                                     \
    asm volatile(                                                            \
        "mma.sync.aligned.m16n8k16.row.col.f32.bf16.bf16.f32 "               \
        "{%0,%1,%2,%3}, {%4,%5,%6,%7}, {%8,%9}, {%0,%1,%2,%3};\n"            \
        : "+f"(d[0]), "+f"(d[1]), "+f"(d[2]), "+f"(d[3])                     \
        : "r"(a[0]), "r"(a[1]), "r"(a[2]), "r"(a[3]), "r"(b[0]), "r"(b[1]))

template <int RELU, int WF32, int WB16>
__global__ void __launch_bounds__(256, 2)
k_gemm_t(const __nv_bfloat16* __restrict__ Ah, const __nv_bfloat16* __restrict__ Al,
         const __nv_bfloat16* __restrict__ Bh, const __nv_bfloat16* __restrict__ Bl,
         const float* __restrict__ bias,
         float* __restrict__ Cf,
         __nv_bfloat16* __restrict__ Chi, __nv_bfloat16* __restrict__ Clo,
         int K, int ldc) {
    __shared__ __nv_bfloat16 sAh[2][BM][KT], sAl[2][BM][KT];
    __shared__ __nv_bfloat16 sBh[2][BN][KT], sBl[2][BN][KT];

    const int tid = threadIdx.x;
    const int lane = tid & 31, wid = tid >> 5;
    const int wm = wid & 3, wn = wid >> 2;      // 4 x 2 warp grid
    const int g = lane >> 2, tg = lane & 3;
    const int row0 = blockIdx.x * BM;
    const int col0 = blockIdx.y * BN;

    // global load mapping (16B per cp.async)
    const int ar = tid >> 1;                    // 0..127
    const int ak = (tid & 1) * 8;
    const int br = (tid & 127) >> 1;            // 0..63
    const __nv_bfloat16* gAh = Ah + (size_t)(row0 + ar) * K + ak;
    const __nv_bfloat16* gAl = Al + (size_t)(row0 + ar) * K + ak;
    const __nv_bfloat16* gB  = (tid < 128 ? Bh : Bl) + (size_t)(col0 + br) * K + ak;

    uint32_t aAh = (uint32_t)__cvta_generic_to_shared(&sAh[0][ar][ak]);
    uint32_t aAl = (uint32_t)__cvta_generic_to_shared(&sAl[0][ar][ak]);
    uint32_t aB  = (uint32_t)__cvta_generic_to_shared(
                       tid < 128 ? &sBh[0][br][ak] : &sBl[0][br][ak]);
    const uint32_t strA = BM * KT * 2;          // bytes per stage
    const uint32_t strB = BN * KT * 2;

    float c[2][4][4];
#pragma unroll
    for (int i = 0; i < 2; i++)
#pragma unroll
        for (int j = 0; j < 4; j++)
#pragma unroll
            for (int k = 0; k < 4; k++) c[i][j][k] = 0.f;

    const int NTk = K / KT;
    // prologue: stage 0
    cpa16(aAh, gAh); cpa16(aAl, gAl); cpa16(aB, gB);
    CP_COMMIT();

    for (int kt = 0; kt < NTk; kt++) {
        CP_WAIT0();
        __syncthreads();
        if (kt + 1 < NTk) {
            uint32_t s = (uint32_t)((kt + 1) & 1);
            cpa16(aAh + s * strA, gAh + (kt + 1) * KT);
            cpa16(aAl + s * strA, gAl + (kt + 1) * KT);
            cpa16(aB  + s * strB, gB  + (kt + 1) * KT);
            CP_COMMIT();
        }
        const int b = kt & 1;

        uint32_t fah[2][4], fal[2][4], fbh[4][2], fbl[4][2];
#pragma unroll
        for (int mt = 0; mt < 2; mt++) {
            int r = wm * 32 + mt * 16 + g;
            fah[mt][0] = *(const uint32_t*)&sAh[b][r][2 * tg];
            fah[mt][1] = *(const uint32_t*)&sAh[b][r + 8][2 * tg];
            fah[mt][2] = *(const uint32_t*)&sAh[b][r][2 * tg + 8];
            fah[mt][3] = *(const uint32_t*)&sAh[b][r + 8][2 * tg + 8];
            fal[mt][0] = *(const uint32_t*)&sAl[b][r][2 * tg];
            fal[mt][1] = *(const uint32_t*)&sAl[b][r + 8][2 * tg];
            fal[mt][2] = *(const uint32_t*)&sAl[b][r][2 * tg + 8];
            fal[mt][3] = *(const uint32_t*)&sAl[b][r + 8][2 * tg + 8];
        }
#pragma unroll
        for (int nt = 0; nt < 4; nt++) {
            int n = wn * 32 + nt * 8 + g;
            fbh[nt][0] = *(const uint32_t*)&sBh[b][n][2 * tg];
            fbh[nt][1] = *(const uint32_t*)&sBh[b][n][2 * tg + 8];
            fbl[nt][0] = *(const uint32_t*)&sBl[b][n][2 * tg];
            fbl[nt][1] = *(const uint32_t*)&sBl[b][n][2 * tg + 8];
        }
#pragma unroll
        for (int mt = 0; mt < 2; mt++)
#pragma unroll
            for (int nt = 0; nt < 4; nt++) {
                MMA_B16(c[mt][nt], fah[mt], fbh[nt]);
                MMA_B16(c[mt][nt], fah[mt], fbl[nt]);
                MMA_B16(c[mt][nt], fal[mt], fbh[nt]);
            }
        __syncthreads();
    }

    // epilogue
#pragma unroll
    for (int mt = 0; mt < 2; mt++) {
        int r0 = row0 + wm * 32 + mt * 16 + g;
        int r1 = r0 + 8;
#pragma unroll
        for (int nt = 0; nt < 4; nt++) {
            int n = col0 + wn * 32 + nt * 8 + 2 * tg;
            float b0 = bias[n], b1 = bias[n + 1];
            float v0 = c[mt][nt][0] + b0, v1 = c[mt][nt][1] + b1;
            float v2 = c[mt][nt][2] + b0, v3 = c[mt][nt][3] + b1;
            if (RELU) {
                v0 = fmaxf(v0, 0.f); v1 = fmaxf(v1, 0.f);
                v2 = fmaxf(v2, 0.f); v3 = fmaxf(v3, 0.f);
            }
            if (WF32) {
                *(float2*)&Cf[(size_t)r0 * ldc + n] = make_float2(v0, v1);
                *(float2*)&Cf[(size_t)r1 * ldc + n] = make_float2(v2, v3);
            }
            if (WB16) {
                __nv_bfloat16 h0, h1, h2, h3, l0, l1, l2, l3;
                split1(v0, h0, l0); split1(v1, h1, l1);
                split1(v2, h2, l2); split1(v3, h3, l3);
                *(__nv_bfloat162*)&Chi[(size_t)r0 * ldc + n] = __nv_bfloat162(h0, h1);
                *(__nv_bfloat162*)&Chi[(size_t)r1 * ldc + n] = __nv_bfloat162(h2, h3);
                *(__nv_bfloat162*)&Clo[(size_t)r0 * ldc + n] = __nv_bfloat162(l0, l1);
                *(__nv_bfloat162*)&Clo[(size_t)r1 * ldc + n] = __nv_bfloat162(l2, l3);
            }
        }
    }
}

// ---------------- tiny GEMM: out[Nx8] = X[Nx64] @ W[8x64]^T + b -------------
__global__ void k_gemm8(const float* __restrict__ X, const float* __restrict__ W,
                        const float* __restrict__ b, float* __restrict__ out) {
    __shared__ float ws[8][64];
    __shared__ float bs[8];
    int t = threadIdx.x;
    for (int i = t; i < 512; i += 256) ws[i >> 6][i & 63] = W[i];
    if (t < 8) bs[t] = b[t];
    __syncthreads();
    int r = blockIdx.x * 256 + t;
    float acc[8];
#pragma unroll
    for (int j = 0; j < 8; j++) acc[j] = bs[j];
    const float* xr = X + (size_t)r * 64;
#pragma unroll
    for (int k = 0; k < 64; k++) {
        float xv = xr[k];
#pragma unroll
        for (int j = 0; j < 8; j++) acc[j] += xv * ws[j][k];
    }
#pragma unroll
    for (int j = 0; j < 8; j++) out[(size_t)r * 8 + j] = acc[j];
}

// ---------------- column mean of ne [N x 128] -> gf [128] -------------------
__global__ void k_zero_gf(float* gf) { gf[threadIdx.x] = 0.f; }

__global__ void k_colsum(const float* __restrict__ ne, float* __restrict__ gf) {
    int col = threadIdx.x;                    // 128
    int r0 = blockIdx.x * 128;
    float s = 0.f;
    for (int r = 0; r < 128; r++) s += ne[(size_t)(r0 + r) * DOUTC + col];
    atomicAdd(&gf[col], s);
}

__global__ void k_scale_gf(float* gf) { gf[threadIdx.x] *= (1.0f / NN); }

// ---------------- launch ----------------------------------------------------
extern "C" void kernel_launch(void* const* d_in, const int* in_sizes, int n_in,
                              void* d_out, int out_size) {
    const float* X      = (const float*)d_in[0];
    const int*   EIDX   = (const int*)d_in[1];
    const float* enc_w1 = (const float*)d_in[2];
    const float* enc_b1 = (const float*)d_in[3];
    const float* enc_w2 = (const float*)d_in[4];
    const float* enc_b2 = (const float*)d_in[5];
    const float* gin_w  = (const float*)d_in[6];
    const float* gin_b  = (const float*)d_in[7];
    const float* gl_w   = (const float*)d_in[8];
    const float* gl_b   = (const float*)d_in[9];
    const float* gout_w = (const float*)d_in[10];
    const float* gout_b = (const float*)d_in[11];
    const float* proj_w = (const float*)d_in[12];
    const float* proj_b = (const float*)d_in[13];
    const float* hc_w1  = (const float*)d_in[14];
    const float* hc_b1  = (const float*)d_in[15];
    const float* hc_w2  = (const float*)d_in[16];
    const float* hc_b2  = (const float*)d_in[17];

    float* out = (float*)d_out;
    float* ne  = out;                               // [N, 128]
    float* hl  = out + (size_t)NN * DOUTC;          // [N, 8]
    float* gf  = hl + (size_t)NN * 8;               // [128]

    static float* bA = nullptr;
    static float* bC = nullptr;
    static void*  bmap = nullptr;
    static __nv_bfloat16 *Phi, *Plo, *Qhi, *Qlo, *Whi, *Wlo;
    if (!bA) {
        cudaGetSymbolAddress((void**)&bA, g_bufA);
        cudaGetSymbolAddress((void**)&bC, g_bufC);
        cudaGetSymbolAddress(&bmap, g_bitmap);
        cudaGetSymbolAddress((void**)&Phi, g_Phi);
        cudaGetSymbolAddress((void**)&Plo, g_Plo);
        cudaGetSymbolAddress((void**)&Qhi, g_Qhi);
        cudaGetSymbolAddress((void**)&Qlo, g_Qlo);
        cudaGetSymbolAddress((void**)&Whi, g_Whi);
        cudaGetSymbolAddress((void**)&Wlo, g_Wlo);
    }

    const int EB = EE / 256;                        // 1536

    // graph build
    k_init<<<NN / 256, 256>>>(EIDX);
    cudaMemsetAsync(bmap, 0, ((size_t)NN * NN) / 8);
    k_dedup<<<EB, 256>>>(EIDX);
    k_scan<<<1, 256>>>();
    k_fill<<<EB, 256>>>();

    // split inputs + weights into bf16 hi/lo
    k_split<<<(NN * 256) / 1024, 256>>>(X, Qhi, Qlo);
    k_split<<<64, 256>>>(enc_w1, Whi + OFF_ENC1, Wlo + OFF_ENC1);
    k_split<<<64, 256>>>(enc_w2, Whi + OFF_ENC2, Wlo + OFF_ENC2);
    k_split<<<64, 256>>>(gin_w,  Whi + OFF_GIN,  Wlo + OFF_GIN);
    k_split<<<192, 256>>>(gl_w,  Whi + OFF_GL,   Wlo + OFF_GL);
    k_split<<<64, 256>>>(gout_w, Whi + OFF_GOUT, Wlo + OFF_GOUT);
    k_split<<<32, 256>>>(proj_w, Whi + OFF_PROJ, Wlo + OFF_PROJ);
    k_split<<<8, 256>>>(hc_w1,   Whi + OFF_HC1,  Wlo + OFF_HC1);

    dim3 g256(NN / BM, 4), g128(NN / BM, 2), g64(NN / BM, 1);

    // node encoder: relu(X@w1)@w2
    k_gemm_t<1, 0, 1><<<g256, 256>>>(Qhi, Qlo, Whi + OFF_ENC1, Wlo + OFF_ENC1,
                                     enc_b1, nullptr, Phi, Plo, 256, 256);
    k_gemm_t<0, 0, 1><<<g256, 256>>>(Phi, Plo, Whi + OFF_ENC2, Wlo + OFF_ENC2,
                                     enc_b2, nullptr, Qhi, Qlo, 256, 256);
    // gnn input proj (spmm needs fp32 too)
    k_gemm_t<1, 1, 1><<<g256, 256>>>(Qhi, Qlo, Whi + OFF_GIN, Wlo + OFF_GIN,
                                     gin_b, bA, Phi, Plo, 256, 256);
    // 3 message-passing layers
    for (int i = 0; i < 3; i++) {
        k_spmm<<<NN, 256>>>(bA, Qhi, Qlo);
        k_gemm_t<1, 1, 1><<<g256, 256>>>(Qhi, Qlo,
                                         Whi + OFF_GL + (size_t)i * 65536,
                                         Wlo + OFF_GL + (size_t)i * 65536,
                                         gl_b + (size_t)i * HH,
                                         bA, Phi, Plo, 256, 256);
    }
    // gnn output proj (no relu)
    k_gemm_t<0, 0, 1><<<g256, 256>>>(Phi, Plo, Whi + OFF_GOUT, Wlo + OFF_GOUT,
                                     gout_b, nullptr, Qhi, Qlo, 256, 256);
    // hierarchy proj -> node_embeddings (fp32 out + split for classifier)
    k_gemm_t<1, 1, 1><<<g128, 256>>>(Qhi, Qlo, Whi + OFF_PROJ, Wlo + OFF_PROJ,
                                     proj_b, ne, Phi, Plo, 256, 128);
    // classifier layer 1 (K=128, M=64, fp32 out only)
    k_gemm_t<1, 1, 0><<<g64, 256>>>(Phi, Plo, Whi + OFF_HC1, Wlo + OFF_HC1,
                                    hc_b1, bC, nullptr, nullptr, 128, 64);
    k_gemm8<<<NN / 256, 256>>>(bC, hc_w2, hc_b2, hl);
    // global mean
    k_zero_gf<<<1, 128>>>(gf);
    k_colsum<<<NN / 128, 128>>>(ne, gf);
    k_scale_gf<<<1, 128>>>(gf);
}

// round 8
// speedup vs baseline: 1.7331x; 1.0916x over previous
#include <cuda_runtime.h>
#include <cuda_bf16.h>
#include <cstdint>

#define NN 12288
#define EE 393216
#define HH 256
#define DOUTC 128

// ---------------- scratch (static device globals; no allocation) -------------
static __device__ unsigned g_bitmap[((size_t)NN * NN) / 32];     // 18.9 MB dedup bitmap
static __device__ int      g_deg[NN];
static __device__ int      g_cursor[NN];
static __device__ int      g_rowptr[NN + 1];
static __device__ float    g_invdeg[NN];
static __device__ int      g_ds[EE];
static __device__ int      g_dd[EE];
static __device__ int      g_col[2 * EE];
static __device__ int      g_ndedup;
static __device__ int      g_is64;
static __device__ float    g_bufA[(size_t)NN * HH];              // fp32 activations (spmm in)
static __device__ float    g_bufC[(size_t)NN * HH];              // fp32 scratch (hc1 out)
// bf16 split activation ping-pong
static __device__ __nv_bfloat16 g_Phi[(size_t)NN * HH];
static __device__ __nv_bfloat16 g_Plo[(size_t)NN * HH];
static __device__ __nv_bfloat16 g_Qhi[(size_t)NN * HH];
static __device__ __nv_bfloat16 g_Qlo[(size_t)NN * HH];
// bf16 split weights (concatenated)
#define OFF_ENC1 0
#define OFF_ENC2 65536
#define OFF_GIN  131072
#define OFF_GL   196608
#define OFF_GOUT 393216
#define OFF_PROJ 458752
#define OFF_HC1  491520
#define WTOT     499712
static __device__ __nv_bfloat16 g_Whi[WTOT];
static __device__ __nv_bfloat16 g_Wlo[WTOT];

// ---------------- setup kernels ---------------------------------------------
__global__ void k_init(const int* __restrict__ p32) {
    int i = blockIdx.x * 256 + threadIdx.x;
    if (i < NN) { g_deg[i] = 0; g_cursor[i] = 0; }
    if (blockIdx.x == 0) {
        __shared__ int anynz;
        if (threadIdx.x == 0) { anynz = 0; g_ndedup = 0; }
        __syncthreads();
        if (p32[2 * threadIdx.x + 1] != 0) atomicOr(&anynz, 1);
        __syncthreads();
        if (threadIdx.x == 0) g_is64 = anynz ? 0 : 1;
    }
}

// warp-aggregated dedup: one counter atomic per warp instead of per edge.
__global__ void k_dedup(const int* __restrict__ p32) {
    int e = blockIdx.x * 256 + threadIdx.x;
    int s = 0, d = 0;
    bool isnew = false;
    if (e < EE) {
        if (g_is64) { s = p32[2 * e]; d = p32[2 * (EE + e)]; }
        else        { s = p32[e];     d = p32[EE + e]; }
        size_t bi = (size_t)s * NN + d;
        unsigned m = 1u << (bi & 31);
        unsigned old = atomicOr(&g_bitmap[bi >> 5], m);
        isnew = !(old & m);
    }
    unsigned mask = __ballot_sync(0xFFFFFFFFu, isnew);
    if (mask) {
        int lane = threadIdx.x & 31;
        int leader = __ffs(mask) - 1;
        int base = 0;
        if (lane == leader) base = atomicAdd(&g_ndedup, __popc(mask));
        base = __shfl_sync(0xFFFFFFFFu, base, leader);
        if (isnew) {
            int idx = base + __popc(mask & ((1u << lane) - 1u));
            g_ds[idx] = s; g_dd[idx] = d;
            atomicAdd(&g_deg[s], 1);
            atomicAdd(&g_deg[d], 1);
        }
    }
}

__global__ void k_scan() {   // 1 block, 256 threads; NN = 256 * 48
    __shared__ int partial[256];
    const int CH = NN / 256;
    int t = threadIdx.x;
    int base = t * CH;
    int s = 0;
    for (int k = 0; k < CH; k++) s += g_deg[base + k];
    partial[t] = s;
    __syncthreads();
    if (t == 0) {
        int acc = 0;
        for (int i = 0; i < 256; i++) { int v = partial[i]; partial[i] = acc; acc += v; }
    }
    __syncthreads();
    int run = partial[t];
    for (int k = 0; k < CH; k++) {
        int dg = g_deg[base + k];
        g_rowptr[base + k] = run;
        g_invdeg[base + k] = 1.0f / ((float)dg + 1e-8f);
        run += dg;
    }
    if (t == 255) g_rowptr[NN] = run;
}

__global__ void k_fill() {
    int i = blockIdx.x * 256 + threadIdx.x;
    if (i >= g_ndedup) return;
    int s = g_ds[i], d = g_dd[i];
    int p = g_rowptr[s] + atomicAdd(&g_cursor[s], 1);
    g_col[p] = d;
    int q = g_rowptr[d] + atomicAdd(&g_cursor[d], 1);
    g_col[q] = s;
}

// ---------------- fp32 -> bf16 hi/lo split ----------------------------------
__device__ __forceinline__ void split1(float v, __nv_bfloat16& h, __nv_bfloat16& l) {
    h = __float2bfloat16_rn(v);
    l = __float2bfloat16_rn(v - __bfloat162float(h));
}

__global__ void k_split(const float* __restrict__ src,
                        __nv_bfloat16* __restrict__ hi,
                        __nv_bfloat16* __restrict__ lo) {
    int i = (blockIdx.x * 256 + threadIdx.x) * 4;
    float4 v = *(const float4*)(src + i);
    __nv_bfloat16 h0, h1, h2, h3, l0, l1, l2, l3;
    split1(v.x, h0, l0); split1(v.y, h1, l1);
    split1(v.z, h2, l2); split1(v.w, h3, l3);
    *(__nv_bfloat162*)(hi + i)     = __nv_bfloat162(h0, h1);
    *(__nv_bfloat162*)(hi + i + 2) = __nv_bfloat162(h2, h3);
    *(__nv_bfloat162*)(lo + i)     = __nv_bfloat162(l0, l1);
    *(__nv_bfloat162*)(lo + i + 2) = __nv_bfloat162(l2, l3);
}

// ---------------- SpMM: y = x + invdeg[row]*sum x[j]; emits bf16 hi/lo ------
// 4 groups x 64 threads; each group pulls one neighbor row as float4s.
__global__ void __launch_bounds__(256) k_spmm(const float* __restrict__ x,
                                              __nv_bfloat16* __restrict__ yh,
                                              __nv_bfloat16* __restrict__ yl) {
    int row = blockIdx.x;
    int t = threadIdx.x;
    int grp = t >> 6;                          // 0..3
    int j4 = (t & 63) * 4;                     // column base 0..252
    int beg = g_rowptr[row], end = g_rowptr[row + 1];
    __shared__ int cs[128];
    __shared__ float red[4][256];
    float ax = 0.f, ay = 0.f, az = 0.f, aw = 0.f;
    for (int c0 = beg; c0 < end; c0 += 128) {
        int n = min(128, end - c0);
        __syncthreads();
        if (t < n) cs[t] = g_col[c0 + t];
        __syncthreads();
#pragma unroll 2
        for (int k = grp; k < n; k += 4) {
            const float4 v = *(const float4*)(x + (size_t)cs[k] * HH + j4);
            ax += v.x; ay += v.y; az += v.z; aw += v.w;
        }
    }
    *(float4*)&red[grp][j4] = make_float4(ax, ay, az, aw);
    __syncthreads();
    float ssum = red[0][t] + red[1][t] + red[2][t] + red[3][t];
    size_t o = (size_t)row * HH + t;
    float v = x[o] + g_invdeg[row] * ssum;
    __nv_bfloat16 h, l; split1(v, h, l);
    yh[o] = h; yl[o] = l;
}

// ---------------- bf16x3 tensor-core GEMM -----------------------------------
#define BM 128
#define BN 64
#define KT 16

__device__ __forceinline__ void cpa16(uint32_t s, const void* g) {
    asm volatile("cp.async.cg.shared.global [%0], [%1], 16;\n" :: "r"(s), "l"(g));
}
#define CP_COMMIT() asm volatile("cp.async.commit_group;\n" ::: "memory")
#define CP_WAIT0()  asm volatile("cp.async.wait_group 0;\n" ::: "memory")

#define MMA_B16(d, a, b)                                                     \
    asm volatile(                                                            \
        "mma.sync.aligned.m16n8k16.row.col.f32.bf16.bf16.f32 "               \
        "{%0,%1,%2,%3}, {%4,%5,%6,%7}, {%8,%9}, {%0,%1,%2,%3};\n"            \
        : "+f"(d[0]), "+f"(d[1]), "+f"(d[2]), "+f"(d[3])                     \
        : "r"(a[0]), "r"(a[1]), "r"(a[2]), "r"(a[3]), "r"(b[0]), "r"(b[1]))

template <int RELU, int WF32, int WB16>
__global__ void __launch_bounds__(256, 2)
k_gemm_t(const __nv_bfloat16* __restrict__ Ah, const __nv_bfloat16* __restrict__ Al,
         const __nv_bfloat16* __restrict__ Bh, const __nv_bfloat16* __restrict__ Bl,
         const float* __restrict__ bias,
         float* __restrict__ Cf,
         __nv_bfloat16* __restrict__ Chi, __nv_bfloat16* __restrict__ Clo,
         int K, int ldc) {
    __shared__ __nv_bfloat16 sAh[2][BM][KT], sAl[2][BM][KT];
    __shared__ __nv_bfloat16 sBh[2][BN][KT], sBl[2][BN][KT];

    const int tid = threadIdx.x;
    const int lane = tid & 31, wid = tid >> 5;
    const int wm = wid & 3, wn = wid >> 2;      // 4 x 2 warp grid
    const int g = lane >> 2, tg = lane & 3;
    const int row0 = blockIdx.x * BM;
    const int col0 = blockIdx.y * BN;

    const int ar = tid >> 1;                    // 0..127
    const int ak = (tid & 1) * 8;
    const int br = (tid & 127) >> 1;            // 0..63
    const __nv_bfloat16* gAh = Ah + (size_t)(row0 + ar) * K + ak;
    const __nv_bfloat16* gAl = Al + (size_t)(row0 + ar) * K + ak;
    const __nv_bfloat16* gB  = (tid < 128 ? Bh : Bl) + (size_t)(col0 + br) * K + ak;

    uint32_t aAh = (uint32_t)__cvta_generic_to_shared(&sAh[0][ar][ak]);
    uint32_t aAl = (uint32_t)__cvta_generic_to_shared(&sAl[0][ar][ak]);
    uint32_t aB  = (uint32_t)__cvta_generic_to_shared(
                       tid < 128 ? &sBh[0][br][ak] : &sBl[0][br][ak]);
    const uint32_t strA = BM * KT * 2;
    const uint32_t strB = BN * KT * 2;

    float c[2][4][4];
#pragma unroll
    for (int i = 0; i < 2; i++)
#pragma unroll
        for (int j = 0; j < 4; j++)
#pragma unroll
            for (int k = 0; k < 4; k++) c[i][j][k] = 0.f;

    const int NTk = K / KT;
    cpa16(aAh, gAh); cpa16(aAl, gAl); cpa16(aB, gB);
    CP_COMMIT();

    for (int kt = 0; kt < NTk; kt++) {
        CP_WAIT0();
        __syncthreads();
        if (kt + 1 < NTk) {
            uint32_t s = (uint32_t)((kt + 1) & 1);
            cpa16(aAh + s * strA, gAh + (kt + 1) * KT);
            cpa16(aAl + s * strA, gAl + (kt + 1) * KT);
            cpa16(aB  + s * strB, gB  + (kt + 1) * KT);
            CP_COMMIT();
        }
        const int b = kt & 1;

        uint32_t fah[2][4], fal[2][4], fbh[4][2], fbl[4][2];
#pragma unroll
        for (int mt = 0; mt < 2; mt++) {
            int r = wm * 32 + mt * 16 + g;
            fah[mt][0] = *(const uint32_t*)&sAh[b][r][2 * tg];
            fah[mt][1] = *(const uint32_t*)&sAh[b][r + 8][2 * tg];
            fah[mt][2] = *(const uint32_t*)&sAh[b][r][2 * tg + 8];
            fah[mt][3] = *(const uint32_t*)&sAh[b][r + 8][2 * tg + 8];
            fal[mt][0] = *(const uint32_t*)&sAl[b][r][2 * tg];
            fal[mt][1] = *(const uint32_t*)&sAl[b][r + 8][2 * tg];
            fal[mt][2] = *(const uint32_t*)&sAl[b][r][2 * tg + 8];
            fal[mt][3] = *(const uint32_t*)&sAl[b][r + 8][2 * tg + 8];
        }
#pragma unroll
        for (int nt = 0; nt < 4; nt++) {
            int n = wn * 32 + nt * 8 + g;
            fbh[nt][0] = *(const uint32_t*)&sBh[b][n][2 * tg];
            fbh[nt][1] = *(const uint32_t*)&sBh[b][n][2 * tg + 8];
            fbl[nt][0] = *(const uint32_t*)&sBl[b][n][2 * tg];
            fbl[nt][1] = *(const uint32_t*)&sBl[b][n][2 * tg + 8];
        }
#pragma unroll
        for (int mt = 0; mt < 2; mt++)
#pragma unroll
            for (int nt = 0; nt < 4; nt++) {
                MMA_B16(c[mt][nt], fah[mt], fbh[nt]);
                MMA_B16(c[mt][nt], fah[mt], fbl[nt]);
                MMA_B16(c[mt][nt], fal[mt], fbh[nt]);
            }
        __syncthreads();
    }

#pragma unroll
    for (int mt = 0; mt < 2; mt++) {
        int r0 = row0 + wm * 32 + mt * 16 + g;
        int r1 = r0 + 8;
#pragma unroll
        for (int nt = 0; nt < 4; nt++) {
            int n = col0 + wn * 32 + nt * 8 + 2 * tg;
            float b0 = bias[n], b1 = bias[n + 1];
            float v0 = c[mt][nt][0] + b0, v1 = c[mt][nt][1] + b1;
            float v2 = c[mt][nt][2] + b0, v3 = c[mt][nt][3] + b1;
            if (RELU) {
                v0 = fmaxf(v0, 0.f); v1 = fmaxf(v1, 0.f);
                v2 = fmaxf(v2, 0.f); v3 = fmaxf(v3, 0.f);
            }
            if (WF32) {
                *(float2*)&Cf[(size_t)r0 * ldc + n] = make_float2(v0, v1);
                *(float2*)&Cf[(size_t)r1 * ldc + n] = make_float2(v2, v3);
            }
            if (WB16) {
                __nv_bfloat16 h0, h1, h2, h3, l0, l1, l2, l3;
                split1(v0, h0, l0); split1(v1, h1, l1);
                split1(v2, h2, l2); split1(v3, h3, l3);
                *(__nv_bfloat162*)&Chi[(size_t)r0 * ldc + n] = __nv_bfloat162(h0, h1);
                *(__nv_bfloat162*)&Chi[(size_t)r1 * ldc + n] = __nv_bfloat162(h2, h3);
                *(__nv_bfloat162*)&Clo[(size_t)r0 * ldc + n] = __nv_bfloat162(l0, l1);
                *(__nv_bfloat162*)&Clo[(size_t)r1 * ldc + n] = __nv_bfloat162(l2, l3);
            }
        }
    }
}

// ---------------- tiny GEMM: out[Nx8] = X[Nx64] @ W[8x64]^T + b -------------
__global__ void k_gemm8(const float* __restrict__ X, const float* __restrict__ W,
                        const float* __restrict__ b, float* __restrict__ out) {
    __shared__ float ws[8][64];
    __shared__ float bs[8];
    int t = threadIdx.x;
    for (int i = t; i < 512; i += 256) ws[i >> 6][i & 63] = W[i];
    if (t < 8) bs[t] = b[t];
    __syncthreads();
    int r = blockIdx.x * 256 + t;
    float acc[8];
#pragma unroll
    for (int j = 0; j < 8; j++) acc[j] = bs[j];
    const float* xr = X + (size_t)r * 64;
#pragma unroll
    for (int k = 0; k < 64; k++) {
        float xv = xr[k];
#pragma unroll
        for (int j = 0; j < 8; j++) acc[j] += xv * ws[j][k];
    }
#pragma unroll
    for (int j = 0; j < 8; j++) out[(size_t)r * 8 + j] = acc[j];
}

// ---------------- column mean of ne [N x 128] -> gf [128] -------------------
__global__ void k_zero_gf(float* gf) { gf[threadIdx.x] = 0.f; }

__global__ void k_colsum(const float* __restrict__ ne, float* __restrict__ gf) {
    int col = threadIdx.x;
    int r0 = blockIdx.x * 128;
    float s = 0.f;
    for (int r = 0; r < 128; r++) s += ne[(size_t)(r0 + r) * DOUTC + col];
    atomicAdd(&gf[col], s);
}

__global__ void k_scale_gf(float* gf) { gf[threadIdx.x] *= (1.0f / NN); }

// ---------------- launch ----------------------------------------------------
extern "C" void kernel_launch(void* const* d_in, const int* in_sizes, int n_in,
                              void* d_out, int out_size) {
    const float* X      = (const float*)d_in[0];
    const int*   EIDX   = (const int*)d_in[1];
    const float* enc_w1 = (const float*)d_in[2];
    const float* enc_b1 = (const float*)d_in[3];
    const float* enc_w2 = (const float*)d_in[4];
    const float* enc_b2 = (const float*)d_in[5];
    const float* gin_w  = (const float*)d_in[6];
    const float* gin_b  = (const float*)d_in[7];
    const float* gl_w   = (const float*)d_in[8];
    const float* gl_b   = (const float*)d_in[9];
    const float* gout_w = (const float*)d_in[10];
    const float* gout_b = (const float*)d_in[11];
    const float* proj_w = (const float*)d_in[12];
    const float* proj_b = (const float*)d_in[13];
    const float* hc_w1  = (const float*)d_in[14];
    const float* hc_b1  = (const float*)d_in[15];
    const float* hc_w2  = (const float*)d_in[16];
    const float* hc_b2  = (const float*)d_in[17];

    float* out = (float*)d_out;
    float* ne  = out;                               // [N, 128]
    float* hl  = out + (size_t)NN * DOUTC;          // [N, 8]
    float* gf  = hl + (size_t)NN * 8;               // [128]

    static float* bA = nullptr;
    static float* bC = nullptr;
    static void*  bmap = nullptr;
    static __nv_bfloat16 *Phi, *Plo, *Qhi, *Qlo, *Whi, *Wlo;
    if (!bA) {
        cudaGetSymbolAddress((void**)&bA, g_bufA);
        cudaGetSymbolAddress((void**)&bC, g_bufC);
        cudaGetSymbolAddress(&bmap, g_bitmap);
        cudaGetSymbolAddress((void**)&Phi, g_Phi);
        cudaGetSymbolAddress((void**)&Plo, g_Plo);
        cudaGetSymbolAddress((void**)&Qhi, g_Qhi);
        cudaGetSymbolAddress((void**)&Qlo, g_Qlo);
        cudaGetSymbolAddress((void**)&Whi, g_Whi);
        cudaGetSymbolAddress((void**)&Wlo, g_Wlo);
    }

    const int EB = EE / 256;                        // 1536

    // graph build (single stream; no stream/event objects)
    k_init<<<NN / 256, 256>>>(EIDX);
    cudaMemsetAsync(bmap, 0, ((size_t)NN * NN) / 8);
    k_dedup<<<EB, 256>>>(EIDX);
    k_scan<<<1, 256>>>();
    k_fill<<<EB, 256>>>();

    // split inputs + weights into bf16 hi/lo
    k_split<<<(NN * 256) / 1024, 256>>>(X, Qhi, Qlo);
    k_split<<<64, 256>>>(enc_w1, Whi + OFF_ENC1, Wlo + OFF_ENC1);
    k_split<<<64, 256>>>(enc_w2, Whi + OFF_ENC2, Wlo + OFF_ENC2);
    k_split<<<64, 256>>>(gin_w,  Whi + OFF_GIN,  Wlo + OFF_GIN);
    k_split<<<192, 256>>>(gl_w,  Whi + OFF_GL,   Wlo + OFF_GL);
    k_split<<<64, 256>>>(gout_w, Whi + OFF_GOUT, Wlo + OFF_GOUT);
    k_split<<<32, 256>>>(proj_w, Whi + OFF_PROJ, Wlo + OFF_PROJ);
    k_split<<<8, 256>>>(hc_w1,   Whi + OFF_HC1,  Wlo + OFF_HC1);

    dim3 g256(NN / BM, 4), g128(NN / BM, 2), g64(NN / BM, 1);

    // node encoder: relu(X@w1)@w2
    k_gemm_t<1, 0, 1><<<g256, 256>>>(Qhi, Qlo, Whi + OFF_ENC1, Wlo + OFF_ENC1,
                                     enc_b1, nullptr, Phi, Plo, 256, 256);
    k_gemm_t<0, 0, 1><<<g256, 256>>>(Phi, Plo, Whi + OFF_ENC2, Wlo + OFF_ENC2,
                                     enc_b2, nullptr, Qhi, Qlo, 256, 256);
    // gnn input proj (spmm needs fp32 too)
    k_gemm_t<1, 1, 1><<<g256, 256>>>(Qhi, Qlo, Whi + OFF_GIN, Wlo + OFF_GIN,
                                     gin_b, bA, Phi, Plo, 256, 256);
    // 3 message-passing layers
    for (int i = 0; i < 3; i++) {
        k_spmm<<<NN, 256>>>(bA, Qhi, Qlo);
        k_gemm_t<1, 1, 1><<<g256, 256>>>(Qhi, Qlo,
                                         Whi + OFF_GL + (size_t)i * 65536,
                                         Wlo + OFF_GL + (size_t)i * 65536,
                                         gl_b + (size_t)i * HH,
                                         bA, Phi, Plo, 256, 256);
    }
    // gnn output proj (no relu)
    k_gemm_t<0, 0, 1><<<g256, 256>>>(Phi, Plo, Whi + OFF_GOUT, Wlo + OFF_GOUT,
                                     gout_b, nullptr, Qhi, Qlo, 256, 256);
    // hierarchy proj -> node_embeddings (fp32 out + split for classifier)
    k_gemm_t<1, 1, 1><<<g128, 256>>>(Qhi, Qlo, Whi + OFF_PROJ, Wlo + OFF_PROJ,
                                     proj_b, ne, Phi, Plo, 256, 128);
    // classifier layer 1 (K=128, M=64, fp32 out only)
    k_gemm_t<1, 1, 0><<<g64, 256>>>(Phi, Plo, Whi + OFF_HC1, Wlo + OFF_HC1,
                                    hc_b1, bC, nullptr, nullptr, 128, 64);
    k_gemm8<<<NN / 256, 256>>>(bC, hc_w2, hc_b2, hl);
    // global mean
    k_zero_gf<<<1, 128>>>(gf);
    k_colsum<<<NN / 128, 128>>>(ne, gf);
    k_scale_gf<<<1, 128>>>(gf);
}

// round 9
// speedup vs baseline: 1.8889x; 1.0899x over previous
#include <cuda_runtime.h>
#include <cuda_bf16.h>
#include <cuda_fp16.h>
#include <cstdint>

#define NN 12288
#define EE 393216
#define HH 256
#define DOUTC 128

// ---------------- scratch (static device globals; no allocation) -------------
static __device__ unsigned g_bitmap[((size_t)NN * NN) / 32];     // 18.9 MB dedup bitmap
static __device__ int      g_deg[NN];
static __device__ int      g_cursor[NN];
static __device__ int      g_rowptr[NN + 1];
static __device__ float    g_invdeg[NN];
static __device__ int      g_ds[EE];
static __device__ int      g_dd[EE];
static __device__ int      g_col[2 * EE];
static __device__ int      g_ndedup;
static __device__ int      g_is64;
static __device__ float    g_bufC[(size_t)NN * HH];              // fp32 scratch (hc1 out)
static __device__ __half   g_xh[(size_t)NN * HH];                // fp16 activations (spmm in)
// bf16 split activation ping-pong
static __device__ __nv_bfloat16 g_Phi[(size_t)NN * HH];
static __device__ __nv_bfloat16 g_Plo[(size_t)NN * HH];
static __device__ __nv_bfloat16 g_Qhi[(size_t)NN * HH];
static __device__ __nv_bfloat16 g_Qlo[(size_t)NN * HH];
// bf16 split weights (concatenated)
#define OFF_ENC1 0
#define OFF_ENC2 65536
#define OFF_GIN  131072
#define OFF_GL   196608
#define OFF_GOUT 393216
#define OFF_PROJ 458752
#define OFF_HC1  491520
#define WTOT     499712
static __device__ __nv_bfloat16 g_Whi[WTOT];
static __device__ __nv_bfloat16 g_Wlo[WTOT];

// ---------------- setup kernels ---------------------------------------------
__global__ void k_init(const int* __restrict__ p32) {
    int i = blockIdx.x * 256 + threadIdx.x;
    if (i < NN) { g_deg[i] = 0; g_cursor[i] = 0; }
    if (blockIdx.x == 0) {
        __shared__ int anynz;
        if (threadIdx.x == 0) { anynz = 0; g_ndedup = 0; }
        __syncthreads();
        if (p32[2 * threadIdx.x + 1] != 0) atomicOr(&anynz, 1);
        __syncthreads();
        if (threadIdx.x == 0) g_is64 = anynz ? 0 : 1;
    }
}

// warp-aggregated dedup: one counter atomic per warp instead of per edge.
__global__ void k_dedup(const int* __restrict__ p32) {
    int e = blockIdx.x * 256 + threadIdx.x;
    int s = 0, d = 0;
    bool isnew = false;
    if (e < EE) {
        if (g_is64) { s = p32[2 * e]; d = p32[2 * (EE + e)]; }
        else        { s = p32[e];     d = p32[EE + e]; }
        size_t bi = (size_t)s * NN + d;
        unsigned m = 1u << (bi & 31);
        unsigned old = atomicOr(&g_bitmap[bi >> 5], m);
        isnew = !(old & m);
    }
    unsigned mask = __ballot_sync(0xFFFFFFFFu, isnew);
    if (mask) {
        int lane = threadIdx.x & 31;
        int leader = __ffs(mask) - 1;
        int base = 0;
        if (lane == leader) base = atomicAdd(&g_ndedup, __popc(mask));
        base = __shfl_sync(0xFFFFFFFFu, base, leader);
        if (isnew) {
            int idx = base + __popc(mask & ((1u << lane) - 1u));
            g_ds[idx] = s; g_dd[idx] = d;
            atomicAdd(&g_deg[s], 1);
            atomicAdd(&g_deg[d], 1);
        }
    }
}

__global__ void k_scan() {   // 1 block, 256 threads; NN = 256 * 48
    __shared__ int partial[256];
    const int CH = NN / 256;
    int t = threadIdx.x;
    int base = t * CH;
    int s = 0;
    for (int k = 0; k < CH; k++) s += g_deg[base + k];
    partial[t] = s;
    __syncthreads();
    if (t == 0) {
        int acc = 0;
        for (int i = 0; i < 256; i++) { int v = partial[i]; partial[i] = acc; acc += v; }
    }
    __syncthreads();
    int run = partial[t];
    for (int k = 0; k < CH; k++) {
        int dg = g_deg[base + k];
        g_rowptr[base + k] = run;
        g_invdeg[base + k] = 1.0f / ((float)dg + 1e-8f);
        run += dg;
    }
    if (t == 255) g_rowptr[NN] = run;
}

__global__ void k_fill() {
    int i = blockIdx.x * 256 + threadIdx.x;
    if (i >= g_ndedup) return;
    int s = g_ds[i], d = g_dd[i];
    int p = g_rowptr[s] + atomicAdd(&g_cursor[s], 1);
    g_col[p] = d;
    int q = g_rowptr[d] + atomicAdd(&g_cursor[d], 1);
    g_col[q] = s;
}

// ---------------- fp32 -> bf16 hi/lo split ----------------------------------
__device__ __forceinline__ void split1(float v, __nv_bfloat16& h, __nv_bfloat16& l) {
    h = __float2bfloat16_rn(v);
    l = __float2bfloat16_rn(v - __bfloat162float(h));
}

__global__ void k_split(const float* __restrict__ src,
                        __nv_bfloat16* __restrict__ hi,
                        __nv_bfloat16* __restrict__ lo) {
    int i = (blockIdx.x * 256 + threadIdx.x) * 4;
    float4 v = *(const float4*)(src + i);
    __nv_bfloat16 h0, h1, h2, h3, l0, l1, l2, l3;
    split1(v.x, h0, l0); split1(v.y, h1, l1);
    split1(v.z, h2, l2); split1(v.w, h3, l3);
    *(__nv_bfloat162*)(hi + i)     = __nv_bfloat162(h0, h1);
    *(__nv_bfloat162*)(hi + i + 2) = __nv_bfloat162(h2, h3);
    *(__nv_bfloat162*)(lo + i)     = __nv_bfloat162(l0, l1);
    *(__nv_bfloat162*)(lo + i + 2) = __nv_bfloat162(l2, l3);
}

// ---------------- SpMM: y = x + invdeg[row]*sum fp16(x[j]) ------------------
// neighbors read fp16 (half traffic); self term reconstructed bf16 hi+lo.
__global__ void __launch_bounds__(256) k_spmm(const __half* __restrict__ xh,
                                              const __nv_bfloat16* __restrict__ shi,
                                              const __nv_bfloat16* __restrict__ slo,
                                              __nv_bfloat16* __restrict__ yh,
                                              __nv_bfloat16* __restrict__ yl) {
    int row = blockIdx.x;
    int t = threadIdx.x;
    int grp = t >> 6;                          // 0..3
    int j4 = (t & 63) * 4;                     // column base (4 halves = 8B)
    int beg = g_rowptr[row], end = g_rowptr[row + 1];
    __shared__ int cs[128];
    __shared__ float red[4][256];
    float ax = 0.f, ay = 0.f, az = 0.f, aw = 0.f;
    for (int c0 = beg; c0 < end; c0 += 128) {
        int n = min(128, end - c0);
        __syncthreads();
        if (t < n) cs[t] = g_col[c0 + t];
        __syncthreads();
#pragma unroll 2
        for (int k = grp; k < n; k += 4) {
            uint2 v = *(const uint2*)(xh + (size_t)cs[k] * HH + j4);
            __half2 p0 = *(__half2*)&v.x;
            __half2 p1 = *(__half2*)&v.y;
            float2 f0 = __half22float2(p0);
            float2 f1 = __half22float2(p1);
            ax += f0.x; ay += f0.y; az += f1.x; aw += f1.y;
        }
    }
    *(float4*)&red[grp][j4] = make_float4(ax, ay, az, aw);
    __syncthreads();
    float ssum = red[0][t] + red[1][t] + red[2][t] + red[3][t];
    size_t o = (size_t)row * HH + t;
    float self = __bfloat162float(shi[o]) + __bfloat162float(slo[o]);
    float v = self + g_invdeg[row] * ssum;
    __nv_bfloat16 h, l; split1(v, h, l);
    yh[o] = h; yl[o] = l;
}

// ---------------- bf16x3 tensor-core GEMM (ldmatrix fragments) ---------------
#define BM 128
#define BN 64
#define KT 16
#define KP 24    // padded row length (48B stride -> conflict-free LDSM)

__device__ __forceinline__ void cpa16(uint32_t s, const void* g) {
    asm volatile("cp.async.cg.shared.global [%0], [%1], 16;\n" :: "r"(s), "l"(g));
}
#define CP_COMMIT() asm volatile("cp.async.commit_group;\n" ::: "memory")
#define CP_WAIT0()  asm volatile("cp.async.wait_group 0;\n" ::: "memory")

__device__ __forceinline__ void ldsm4(uint32_t& r0, uint32_t& r1, uint32_t& r2,
                                      uint32_t& r3, const void* p) {
    uint32_t a = (uint32_t)__cvta_generic_to_shared(p);
    asm volatile("ldmatrix.sync.aligned.m8n8.x4.shared.b16 {%0,%1,%2,%3}, [%4];\n"
                 : "=r"(r0), "=r"(r1), "=r"(r2), "=r"(r3) : "r"(a));
}

#define MMA_B16(d, a, b)                                                     \
    asm volatile(                                                            \
        "mma.sync.aligned.m16n8k16.row.col.f32.bf16.bf16.f32 "               \
        "{%0,%1,%2,%3}, {%4,%5,%6,%7}, {%8,%9}, {%0,%1,%2,%3};\n"            \
        : "+f"(d[0]), "+f"(d[1]), "+f"(d[2]), "+f"(d[3])                     \
        : "r"(a[0]), "r"(a[1]), "r"(a[2]), "r"(a[3]), "r"(b[0]), "r"(b[1]))

template <int RELU, int WF32, int WB16, int WH16>
__global__ void __launch_bounds__(256, 2)
k_gemm_t(const __nv_bfloat16* __restrict__ Ah, const __nv_bfloat16* __restrict__ Al,
         const __nv_bfloat16* __restrict__ Bh, const __nv_bfloat16* __restrict__ Bl,
         const float* __restrict__ bias,
         float* __restrict__ Cf,
         __nv_bfloat16* __restrict__ Chi, __nv_bfloat16* __restrict__ Clo,
         __half* __restrict__ Ch16,
         int K, int ldc) {
    __shared__ __nv_bfloat16 sAh[2][BM][KP], sAl[2][BM][KP];
    __shared__ __nv_bfloat16 sBh[2][BN][KP], sBl[2][BN][KP];

    const int tid = threadIdx.x;
    const int lane = tid & 31, wid = tid >> 5;
    const int wm = wid & 3, wn = wid >> 2;      // 4 x 2 warp grid
    const int g = lane >> 2, tg = lane & 3;
    const int lsel = lane & 15, lhalf = lane >> 4;
    const int row0 = blockIdx.x * BM;
    const int col0 = blockIdx.y * BN;

    const int ar = tid >> 1;                    // 0..127
    const int ak = (tid & 1) * 8;
    const int br = (tid & 127) >> 1;            // 0..63
    const __nv_bfloat16* gAh = Ah + (size_t)(row0 + ar) * K + ak;
    const __nv_bfloat16* gAl = Al + (size_t)(row0 + ar) * K + ak;
    const __nv_bfloat16* gB  = (tid < 128 ? Bh : Bl) + (size_t)(col0 + br) * K + ak;

    uint32_t aAh = (uint32_t)__cvta_generic_to_shared(&sAh[0][ar][ak]);
    uint32_t aAl = (uint32_t)__cvta_generic_to_shared(&sAl[0][ar][ak]);
    uint32_t aB  = (uint32_t)__cvta_generic_to_shared(
                       tid < 128 ? &sBh[0][br][ak] : &sBl[0][br][ak]);
    const uint32_t strA = BM * KP * 2;
    const uint32_t strB = BN * KP * 2;

    float c[2][4][4];
#pragma unroll
    for (int i = 0; i < 2; i++)
#pragma unroll
        for (int j = 0; j < 4; j++)
#pragma unroll
            for (int k = 0; k < 4; k++) c[i][j][k] = 0.f;

    const int NTk = K / KT;
    cpa16(aAh, gAh); cpa16(aAl, gAl); cpa16(aB, gB);
    CP_COMMIT();

    for (int kt = 0; kt < NTk; kt++) {
        CP_WAIT0();
        __syncthreads();
        if (kt + 1 < NTk) {
            uint32_t s = (uint32_t)((kt + 1) & 1);
            cpa16(aAh + s * strA, gAh + (kt + 1) * KT);
            cpa16(aAl + s * strA, gAl + (kt + 1) * KT);
            cpa16(aB  + s * strB, gB  + (kt + 1) * KT);
            CP_COMMIT();
        }
        const int b = kt & 1;

        uint32_t fah[2][4], fal[2][4], fbh[4][2], fbl[4][2];
#pragma unroll
        for (int mt = 0; mt < 2; mt++) {
            ldsm4(fah[mt][0], fah[mt][1], fah[mt][2], fah[mt][3],
                  &sAh[b][wm * 32 + mt * 16 + lsel][lhalf * 8]);
            ldsm4(fal[mt][0], fal[mt][1], fal[mt][2], fal[mt][3],
                  &sAl[b][wm * 32 + mt * 16 + lsel][lhalf * 8]);
        }
#pragma unroll
        for (int pr = 0; pr < 2; pr++) {
            uint32_t q0, q1, q2, q3;
            ldsm4(q0, q1, q2, q3, &sBh[b][wn * 32 + pr * 16 + lsel][lhalf * 8]);
            fbh[2 * pr][0] = q0; fbh[2 * pr + 1][0] = q1;
            fbh[2 * pr][1] = q2; fbh[2 * pr + 1][1] = q3;
            ldsm4(q0, q1, q2, q3, &sBl[b][wn * 32 + pr * 16 + lsel][lhalf * 8]);
            fbl[2 * pr][0] = q0; fbl[2 * pr + 1][0] = q1;
            fbl[2 * pr][1] = q2; fbl[2 * pr + 1][1] = q3;
        }
#pragma unroll
        for (int mt = 0; mt < 2; mt++)
#pragma unroll
            for (int nt = 0; nt < 4; nt++) {
                MMA_B16(c[mt][nt], fah[mt], fbh[nt]);
                MMA_B16(c[mt][nt], fah[mt], fbl[nt]);
                MMA_B16(c[mt][nt], fal[mt], fbh[nt]);
            }
        __syncthreads();
    }

#pragma unroll
    for (int mt = 0; mt < 2; mt++) {
        int r0 = row0 + wm * 32 + mt * 16 + g;
        int r1 = r0 + 8;
#pragma unroll
        for (int nt = 0; nt < 4; nt++) {
            int n = col0 + wn * 32 + nt * 8 + 2 * tg;
            float b0 = bias[n], b1 = bias[n + 1];
            float v0 = c[mt][nt][0] + b0, v1 = c[mt][nt][1] + b1;
            float v2 = c[mt][nt][2] + b0, v3 = c[mt][nt][3] + b1;
            if (RELU) {
                v0 = fmaxf(v0, 0.f); v1 = fmaxf(v1, 0.f);
                v2 = fmaxf(v2, 0.f); v3 = fmaxf(v3, 0.f);
            }
            if (WF32) {
                *(float2*)&Cf[(size_t)r0 * ldc + n] = make_float2(v0, v1);
                *(float2*)&Cf[(size_t)r1 * ldc + n] = make_float2(v2, v3);
            }
            if (WH16) {
                *(__half2*)&Ch16[(size_t)r0 * ldc + n] = __floats2half2_rn(v0, v1);
                *(__half2*)&Ch16[(size_t)r1 * ldc + n] = __floats2half2_rn(v2, v3);
            }
            if (WB16) {
                __nv_bfloat16 h0, h1, h2, h3, l0, l1, l2, l3;
                split1(v0, h0, l0); split1(v1, h1, l1);
                split1(v2, h2, l2); split1(v3, h3, l3);
                *(__nv_bfloat162*)&Chi[(size_t)r0 * ldc + n] = __nv_bfloat162(h0, h1);
                *(__nv_bfloat162*)&Chi[(size_t)r1 * ldc + n] = __nv_bfloat162(h2, h3);
                *(__nv_bfloat162*)&Clo[(size_t)r0 * ldc + n] = __nv_bfloat162(l0, l1);
                *(__nv_bfloat162*)&Clo[(size_t)r1 * ldc + n] = __nv_bfloat162(l2, l3);
            }
        }
    }
}

// ---------------- tiny GEMM: out[Nx8] = X[Nx64] @ W[8x64]^T + b -------------
__global__ void k_gemm8(const float* __restrict__ X, const float* __restrict__ W,
                        const float* __restrict__ b, float* __restrict__ out) {
    __shared__ float ws[8][64];
    __shared__ float bs[8];
    int t = threadIdx.x;
    for (int i = t; i < 512; i += 256) ws[i >> 6][i & 63] = W[i];
    if (t < 8) bs[t] = b[t];
    __syncthreads();
    int r = blockIdx.x * 256 + t;
    float acc[8];
#pragma unroll
    for (int j = 0; j < 8; j++) acc[j] = bs[j];
    const float* xr = X + (size_t)r * 64;
#pragma unroll
    for (int k = 0; k < 64; k++) {
        float xv = xr[k];
#pragma unroll
        for (int j = 0; j < 8; j++) acc[j] += xv * ws[j][k];
    }
#pragma unroll
    for (int j = 0; j < 8; j++) out[(size_t)r * 8 + j] = acc[j];
}

// ---------------- column mean of ne [N x 128] -> gf [128] -------------------
__global__ void k_zero_gf(float* gf) { gf[threadIdx.x] = 0.f; }

__global__ void k_colsum(const float* __restrict__ ne, float* __restrict__ gf) {
    int col = threadIdx.x;
    int r0 = blockIdx.x * 128;
    float s = 0.f;
    for (int r = 0; r < 128; r++) s += ne[(size_t)(r0 + r) * DOUTC + col];
    atomicAdd(&gf[col], s);
}

__global__ void k_scale_gf(float* gf) { gf[threadIdx.x] *= (1.0f / NN); }

// ---------------- launch ----------------------------------------------------
extern "C" void kernel_launch(void* const* d_in, const int* in_sizes, int n_in,
                              void* d_out, int out_size) {
    const float* X      = (const float*)d_in[0];
    const int*   EIDX   = (const int*)d_in[1];
    const float* enc_w1 = (const float*)d_in[2];
    const float* enc_b1 = (const float*)d_in[3];
    const float* enc_w2 = (const float*)d_in[4];
    const float* enc_b2 = (const float*)d_in[5];
    const float* gin_w  = (const float*)d_in[6];
    const float* gin_b  = (const float*)d_in[7];
    const float* gl_w   = (const float*)d_in[8];
    const float* gl_b   = (const float*)d_in[9];
    const float* gout_w = (const float*)d_in[10];
    const float* gout_b = (const float*)d_in[11];
    const float* proj_w = (const float*)d_in[12];
    const float* proj_b = (const float*)d_in[13];
    const float* hc_w1  = (const float*)d_in[14];
    const float* hc_b1  = (const float*)d_in[15];
    const float* hc_w2  = (const float*)d_in[16];
    const float* hc_b2  = (const float*)d_in[17];

    float* out = (float*)d_out;
    float* ne  = out;                               // [N, 128]
    float* hl  = out + (size_t)NN * DOUTC;          // [N, 8]
    float* gf  = hl + (size_t)NN * 8;               // [128]

    static float* bC = nullptr;
    static void*  bmap = nullptr;
    static __half* xh = nullptr;
    static __nv_bfloat16 *Phi, *Plo, *Qhi, *Qlo, *Whi, *Wlo;
    if (!bC) {
        cudaGetSymbolAddress((void**)&bC, g_bufC);
        cudaGetSymbolAddress(&bmap, g_bitmap);
        cudaGetSymbolAddress((void**)&xh, g_xh);
        cudaGetSymbolAddress((void**)&Phi, g_Phi);
        cudaGetSymbolAddress((void**)&Plo, g_Plo);
        cudaGetSymbolAddress((void**)&Qhi, g_Qhi);
        cudaGetSymbolAddress((void**)&Qlo, g_Qlo);
        cudaGetSymbolAddress((void**)&Whi, g_Whi);
        cudaGetSymbolAddress((void**)&Wlo, g_Wlo);
    }

    const int EB = EE / 256;                        // 1536

    // graph build
    k_init<<<NN / 256, 256>>>(EIDX);
    cudaMemsetAsync(bmap, 0, ((size_t)NN * NN) / 8);
    k_dedup<<<EB, 256>>>(EIDX);
    k_scan<<<1, 256>>>();
    k_fill<<<EB, 256>>>();

    // split inputs + weights into bf16 hi/lo
    k_split<<<(NN * 256) / 1024, 256>>>(X, Qhi, Qlo);
    k_split<<<64, 256>>>(enc_w1, Whi + OFF_ENC1, Wlo + OFF_ENC1);
    k_split<<<64, 256>>>(enc_w2, Whi + OFF_ENC2, Wlo + OFF_ENC2);
    k_split<<<64, 256>>>(gin_w,  Whi + OFF_GIN,  Wlo + OFF_GIN);
    k_split<<<192, 256>>>(gl_w,  Whi + OFF_GL,   Wlo + OFF_GL);
    k_split<<<64, 256>>>(gout_w, Whi + OFF_GOUT, Wlo + OFF_GOUT);
    k_split<<<32, 256>>>(proj_w, Whi + OFF_PROJ, Wlo + OFF_PROJ);
    k_split<<<8, 256>>>(hc_w1,   Whi + OFF_HC1,  Wlo + OFF_HC1);

    dim3 g256(NN / BM, 4), g128(NN / BM, 2), g64(NN / BM, 1);

    // node encoder: relu(X@w1)@w2
    k_gemm_t<1, 0, 1, 0><<<g256, 256>>>(Qhi, Qlo, Whi + OFF_ENC1, Wlo + OFF_ENC1,
                                        enc_b1, nullptr, Phi, Plo, nullptr, 256, 256);
    k_gemm_t<0, 0, 1, 0><<<g256, 256>>>(Phi, Plo, Whi + OFF_ENC2, Wlo + OFF_ENC2,
                                        enc_b2, nullptr, Qhi, Qlo, nullptr, 256, 256);
    // gnn input proj (spmm needs fp16 neighbors + bf16 pair self-term)
    k_gemm_t<1, 0, 1, 1><<<g256, 256>>>(Qhi, Qlo, Whi + OFF_GIN, Wlo + OFF_GIN,
                                        gin_b, nullptr, Phi, Plo, xh, 256, 256);
    // 3 message-passing layers
    for (int i = 0; i < 3; i++) {
        k_spmm<<<NN, 256>>>(xh, Phi, Plo, Qhi, Qlo);
        k_gemm_t<1, 0, 1, 1><<<g256, 256>>>(Qhi, Qlo,
                                            Whi + OFF_GL + (size_t)i * 65536,
                                            Wlo + OFF_GL + (size_t)i * 65536,
                                            gl_b + (size_t)i * HH,
                                            nullptr, Phi, Plo, xh, 256, 256);
    }
    // gnn output proj (no relu)
    k_gemm_t<0, 0, 1, 0><<<g256, 256>>>(Phi, Plo, Whi + OFF_GOUT, Wlo + OFF_GOUT,
                                        gout_b, nullptr, Qhi, Qlo, nullptr, 256, 256);
    // hierarchy proj -> node_embeddings (fp32 out + split for classifier)
    k_gemm_t<1, 1, 1, 0><<<g128, 256>>>(Qhi, Qlo, Whi + OFF_PROJ, Wlo + OFF_PROJ,
                                        proj_b, ne, Phi, Plo, nullptr, 256, 128);
    // classifier layer 1 (K=128, M=64, fp32 out only)
    k_gemm_t<1, 1, 0, 0><<<g64, 256>>>(Phi, Plo, Whi + OFF_HC1, Wlo + OFF_HC1,
                                       hc_b1, bC, nullptr, nullptr, nullptr, 128, 64);
    k_gemm8<<<NN / 256, 256>>>(bC, hc_w2, hc_b2, hl);
    // global mean
    k_zero_gf<<<1, 128>>>(gf);
    k_colsum<<<NN / 128, 128>>>(ne, gf);
    k_scale_gf<<<1, 128>>>(gf);
}

// round 10
// speedup vs baseline: 2.0898x; 1.1063x over previous
#include <cuda_runtime.h>
#include <cuda_bf16.h>
#include <cuda_fp16.h>
#include <cstdint>

#define NN 12288
#define EE 393216
#define HH 256
#define DOUTC 128

// ---------------- scratch (static device globals; no allocation) -------------
static __device__ unsigned g_bitmap[((size_t)NN * NN) / 32];     // 18.9 MB dedup bitmap
static __device__ int      g_deg[NN];
static __device__ int      g_cursor[NN];
static __device__ int      g_rowptr[NN + 1];
static __device__ float    g_invdeg[NN];
static __device__ int      g_ds[EE];
static __device__ int      g_dd[EE];
static __device__ int      g_col[2 * EE];
static __device__ int      g_ndedup;
static __device__ int      g_is64;
static __device__ float    g_bufC[(size_t)NN * HH];              // fp32 scratch (hc1 out)
static __device__ __half   g_xh[(size_t)NN * HH];                // fp16 activations (spmm in)
// bf16 split activation ping-pong
static __device__ __nv_bfloat16 g_Phi[(size_t)NN * HH];
static __device__ __nv_bfloat16 g_Plo[(size_t)NN * HH];
static __device__ __nv_bfloat16 g_Qhi[(size_t)NN * HH];
static __device__ __nv_bfloat16 g_Qlo[(size_t)NN * HH];
// bf16 split weights (concatenated)
#define OFF_ENC1 0
#define OFF_ENC2 65536
#define OFF_GIN  131072
#define OFF_GL   196608
#define OFF_GOUT 393216
#define OFF_PROJ 458752
#define OFF_HC1  491520
#define WTOT     499712
static __device__ __nv_bfloat16 g_Whi[WTOT];
static __device__ __nv_bfloat16 g_Wlo[WTOT];

// ---------------- fp32 -> bf16 hi/lo split ----------------------------------
__device__ __forceinline__ void split1(float v, __nv_bfloat16& h, __nv_bfloat16& l) {
    h = __float2bfloat16_rn(v);
    l = __float2bfloat16_rn(v - __bfloat162float(h));
}

// ---------------- mega setup: all splits + init + is64 detect ----------------
// blocks [0,3072): X split; [3072,3560): weight splits; [3560,3608): init arrays
__global__ void k_split_all(const float* __restrict__ X, const int* __restrict__ p32,
                            const float* __restrict__ w_enc1, const float* __restrict__ w_enc2,
                            const float* __restrict__ w_gin,  const float* __restrict__ w_gl,
                            const float* __restrict__ w_gout, const float* __restrict__ w_proj,
                            const float* __restrict__ w_hc1,
                            __nv_bfloat16* __restrict__ Qhi, __nv_bfloat16* __restrict__ Qlo,
                            __nv_bfloat16* __restrict__ Whi, __nv_bfloat16* __restrict__ Wlo) {
    int b = blockIdx.x;
    int t = threadIdx.x;
    if (b >= 3560) {                    // init segment
        int i = (b - 3560) * 256 + t;
        g_deg[i] = 0; g_cursor[i] = 0;
        if (b == 3560) {
            __shared__ int anynz;
            if (t == 0) { anynz = 0; g_ndedup = 0; }
            __syncthreads();
            if (p32[2 * t + 1] != 0) atomicOr(&anynz, 1);
            __syncthreads();
            if (t == 0) g_is64 = anynz ? 0 : 1;
        }
        return;
    }
    const float* src;
    __nv_bfloat16 *hi, *lo;
    if (b < 3072) { src = X; hi = Qhi; lo = Qlo; }
    else {
        b -= 3072;
        int woff;
        if      (b < 64)  { src = w_enc1; woff = OFF_ENC1; }
        else if (b < 128) { src = w_enc2; woff = OFF_ENC2; b -= 64; }
        else if (b < 192) { src = w_gin;  woff = OFF_GIN;  b -= 128; }
        else if (b < 384) { src = w_gl;   woff = OFF_GL;   b -= 192; }
        else if (b < 448) { src = w_gout; woff = OFF_GOUT; b -= 384; }
        else if (b < 480) { src = w_proj; woff = OFF_PROJ; b -= 448; }
        else              { src = w_hc1;  woff = OFF_HC1;  b -= 480; }
        hi = Whi + woff; lo = Wlo + woff;
    }
    int i = (b * 256 + t) * 4;
    float4 v = *(const float4*)(src + i);
    __nv_bfloat16 h0, h1, h2, h3, l0, l1, l2, l3;
    split1(v.x, h0, l0); split1(v.y, h1, l1);
    split1(v.z, h2, l2); split1(v.w, h3, l3);
    *(__nv_bfloat162*)(hi + i)     = __nv_bfloat162(h0, h1);
    *(__nv_bfloat162*)(hi + i + 2) = __nv_bfloat162(h2, h3);
    *(__nv_bfloat162*)(lo + i)     = __nv_bfloat162(l0, l1);
    *(__nv_bfloat162*)(lo + i + 2) = __nv_bfloat162(l2, l3);
}

// warp-aggregated dedup: one counter atomic per warp instead of per edge.
__global__ void k_dedup(const int* __restrict__ p32) {
    int e = blockIdx.x * 256 + threadIdx.x;
    int s = 0, d = 0;
    bool isnew = false;
    if (e < EE) {
        if (g_is64) { s = p32[2 * e]; d = p32[2 * (EE + e)]; }
        else        { s = p32[e];     d = p32[EE + e]; }
        size_t bi = (size_t)s * NN + d;
        unsigned m = 1u << (bi & 31);
        unsigned old = atomicOr(&g_bitmap[bi >> 5], m);
        isnew = !(old & m);
    }
    unsigned mask = __ballot_sync(0xFFFFFFFFu, isnew);
    if (mask) {
        int lane = threadIdx.x & 31;
        int leader = __ffs(mask) - 1;
        int base = 0;
        if (lane == leader) base = atomicAdd(&g_ndedup, __popc(mask));
        base = __shfl_sync(0xFFFFFFFFu, base, leader);
        if (isnew) {
            int idx = base + __popc(mask & ((1u << lane) - 1u));
            g_ds[idx] = s; g_dd[idx] = d;
            atomicAdd(&g_deg[s], 1);
            atomicAdd(&g_deg[d], 1);
        }
    }
}

__global__ void k_scan() {   // 1 block, 256 threads; NN = 256 * 48
    __shared__ int partial[256];
    const int CH = NN / 256;
    int t = threadIdx.x;
    int base = t * CH;
    int s = 0;
    for (int k = 0; k < CH; k++) s += g_deg[base + k];
    partial[t] = s;
    __syncthreads();
    if (t == 0) {
        int acc = 0;
        for (int i = 0; i < 256; i++) { int v = partial[i]; partial[i] = acc; acc += v; }
    }
    __syncthreads();
    int run = partial[t];
    for (int k = 0; k < CH; k++) {
        int dg = g_deg[base + k];
        g_rowptr[base + k] = run;
        g_invdeg[base + k] = 1.0f / ((float)dg + 1e-8f);
        run += dg;
    }
    if (t == 255) g_rowptr[NN] = run;
}

__global__ void k_fill() {
    int i = blockIdx.x * 256 + threadIdx.x;
    if (i >= g_ndedup) return;
    int s = g_ds[i], d = g_dd[i];
    int p = g_rowptr[s] + atomicAdd(&g_cursor[s], 1);
    g_col[p] = d;
    int q = g_rowptr[d] + atomicAdd(&g_cursor[d], 1);
    g_col[q] = s;
}

// ---------------- SpMM: y = x + invdeg[row]*sum fp16(x[j]) ------------------
__global__ void __launch_bounds__(256) k_spmm(const __half* __restrict__ xh,
                                              const __nv_bfloat16* __restrict__ shi,
                                              const __nv_bfloat16* __restrict__ slo,
                                              __nv_bfloat16* __restrict__ yh,
                                              __nv_bfloat16* __restrict__ yl) {
    int row = blockIdx.x;
    int t = threadIdx.x;
    int grp = t >> 6;                          // 0..3
    int j4 = (t & 63) * 4;                     // column base (4 halves = 8B)
    int beg = g_rowptr[row], end = g_rowptr[row + 1];
    __shared__ int cs[128];
    __shared__ float red[4][256];
    float ax = 0.f, ay = 0.f, az = 0.f, aw = 0.f;
    for (int c0 = beg; c0 < end; c0 += 128) {
        int n = min(128, end - c0);
        __syncthreads();
        if (t < n) cs[t] = g_col[c0 + t];
        __syncthreads();
#pragma unroll 2
        for (int k = grp; k < n; k += 4) {
            uint2 v = *(const uint2*)(xh + (size_t)cs[k] * HH + j4);
            __half2 p0 = *(__half2*)&v.x;
            __half2 p1 = *(__half2*)&v.y;
            float2 f0 = __half22float2(p0);
            float2 f1 = __half22float2(p1);
            ax += f0.x; ay += f0.y; az += f1.x; aw += f1.y;
        }
    }
    *(float4*)&red[grp][j4] = make_float4(ax, ay, az, aw);
    __syncthreads();
    float ssum = red[0][t] + red[1][t] + red[2][t] + red[3][t];
    size_t o = (size_t)row * HH + t;
    float self = __bfloat162float(shi[o]) + __bfloat162float(slo[o]);
    float v = self + g_invdeg[row] * ssum;
    __nv_bfloat16 h, l; split1(v, h, l);
    yh[o] = h; yl[o] = l;
}

// ---------------- bf16x3 tensor-core GEMM: 3-stage pipeline, KT=32 ----------
#define BM 128
#define BN 64
#define KT 32
#define KP 40                     // 80B row stride -> conflict-free LDSM
#define STAGE_E 15360             // elems per stage: A 2*5120 + B 2*2560
#define AOFF_H 0
#define AOFF_L 5120
#define BOFF_H 10240
#define BOFF_L 12800
#define SMEM_GEMM (3 * STAGE_E * 2)   // 92160 bytes

__device__ __forceinline__ void cpa16(uint32_t s, const void* g) {
    asm volatile("cp.async.cg.shared.global [%0], [%1], 16;\n" :: "r"(s), "l"(g));
}
#define CP_COMMIT() asm volatile("cp.async.commit_group;\n" ::: "memory")
#define CP_WAIT0()  asm volatile("cp.async.wait_group 0;\n" ::: "memory")
#define CP_WAIT1()  asm volatile("cp.async.wait_group 1;\n" ::: "memory")

__device__ __forceinline__ void ldsm4(uint32_t& r0, uint32_t& r1, uint32_t& r2,
                                      uint32_t& r3, const void* p) {
    uint32_t a = (uint32_t)__cvta_generic_to_shared(p);
    asm volatile("ldmatrix.sync.aligned.m8n8.x4.shared.b16 {%0,%1,%2,%3}, [%4];\n"
                 : "=r"(r0), "=r"(r1), "=r"(r2), "=r"(r3) : "r"(a));
}

#define MMA_B16(d, a, b)                                                     \
    asm volatile(                                                            \
        "mma.sync.aligned.m16n8k16.row.col.f32.bf16.bf16.f32 "               \
        "{%0,%1,%2,%3}, {%4,%5,%6,%7}, {%8,%9}, {%0,%1,%2,%3};\n"            \
        : "+f"(d[0]), "+f"(d[1]), "+f"(d[2]), "+f"(d[3])                     \
        : "r"(a[0]), "r"(a[1]), "r"(a[2]), "r"(a[3]), "r"(b[0]), "r"(b[1]))

template <int RELU, int WF32, int WB16, int WH16>
__global__ void __launch_bounds__(256, 2)
k_gemm_t(const __nv_bfloat16* __restrict__ Ah, const __nv_bfloat16* __restrict__ Al,
         const __nv_bfloat16* __restrict__ Bh, const __nv_bfloat16* __restrict__ Bl,
         const float* __restrict__ bias,
         float* __restrict__ Cf,
         __nv_bfloat16* __restrict__ Chi, __nv_bfloat16* __restrict__ Clo,
         __half* __restrict__ Ch16,
         int K, int ldc) {
    extern __shared__ __nv_bfloat16 sm[];

    const int tid = threadIdx.x;
    const int lane = tid & 31, wid = tid >> 5;
    const int wm = wid & 3, wn = wid >> 2;      // 4 x 2 warp grid
    const int g = lane >> 2, tg = lane & 3;
    const int lsel = lane & 15, lhalf = lane >> 4;
    const int row0 = blockIdx.x * BM;
    const int col0 = blockIdx.y * BN;

    // global->smem mapping: A rows r0, r0+64 at k-chunk kc; B rows rb, rb+32
    const int r0 = tid >> 2;                    // 0..63
    const int kc = (tid & 3) * 8;
    const int rb = (tid & 127) >> 2;            // 0..31
    const bool bhi = (tid < 128);
    const __nv_bfloat16* gAh0 = Ah + (size_t)(row0 + r0) * K + kc;
    const __nv_bfloat16* gAl0 = Al + (size_t)(row0 + r0) * K + kc;
    const __nv_bfloat16* gB0  = (bhi ? Bh : Bl) + (size_t)(col0 + rb) * K + kc;
    const int aA0 = r0 * KP + kc, aA1 = (r0 + 64) * KP + kc;
    const int aB0 = (bhi ? BOFF_H : BOFF_L) + rb * KP + kc;
    const int aB1 = aB0 + 32 * KP;
    uint32_t smu = (uint32_t)__cvta_generic_to_shared(sm);

    float c[2][4][4];
#pragma unroll
    for (int i = 0; i < 2; i++)
#pragma unroll
        for (int j = 0; j < 4; j++)
#pragma unroll
            for (int k = 0; k < 4; k++) c[i][j][k] = 0.f;

    const int NTk = K / KT;

#define LOAD_STAGE(kt)                                                        \
    do {                                                                      \
        int _s = (kt) % 3;                                                    \
        uint32_t _b = smu + (uint32_t)(_s * STAGE_E) * 2;                     \
        int _ko = (kt) * KT;                                                  \
        cpa16(_b + (AOFF_H + aA0) * 2, gAh0 + _ko);                           \
        cpa16(_b + (AOFF_H + aA1) * 2, gAh0 + (size_t)64 * K + _ko);          \
        cpa16(_b + (AOFF_L + aA0) * 2, gAl0 + _ko);                           \
        cpa16(_b + (AOFF_L + aA1) * 2, gAl0 + (size_t)64 * K + _ko);          \
        cpa16(_b + aB0 * 2, gB0 + _ko);                                       \
        cpa16(_b + aB1 * 2, gB0 + (size_t)32 * K + _ko);                      \
        CP_COMMIT();                                                          \
    } while (0)

    LOAD_STAGE(0);
    if (NTk > 1) LOAD_STAGE(1);

    for (int kt = 0; kt < NTk; kt++) {
        if (kt < NTk - 1) CP_WAIT1(); else CP_WAIT0();
        __syncthreads();
        if (kt + 2 < NTk) LOAD_STAGE(kt + 2);
        const int s = kt % 3;
        __nv_bfloat16* stg = sm + s * STAGE_E;
#pragma unroll
        for (int ks = 0; ks < KT; ks += 16) {
            uint32_t fah[2][4], fal[2][4], fbh[4][2], fbl[4][2];
#pragma unroll
            for (int mt = 0; mt < 2; mt++) {
                int ar = wm * 32 + mt * 16 + lsel;
                ldsm4(fah[mt][0], fah[mt][1], fah[mt][2], fah[mt][3],
                      stg + AOFF_H + ar * KP + ks + lhalf * 8);
                ldsm4(fal[mt][0], fal[mt][1], fal[mt][2], fal[mt][3],
                      stg + AOFF_L + ar * KP + ks + lhalf * 8);
            }
#pragma unroll
            for (int pr = 0; pr < 2; pr++) {
                int br = wn * 32 + pr * 16 + lsel;
                uint32_t q0, q1, q2, q3;
                ldsm4(q0, q1, q2, q3, stg + BOFF_H + br * KP + ks + lhalf * 8);
                fbh[2 * pr][0] = q0; fbh[2 * pr + 1][0] = q1;
                fbh[2 * pr][1] = q2; fbh[2 * pr + 1][1] = q3;
                ldsm4(q0, q1, q2, q3, stg + BOFF_L + br * KP + ks + lhalf * 8);
                fbl[2 * pr][0] = q0; fbl[2 * pr + 1][0] = q1;
                fbl[2 * pr][1] = q2; fbl[2 * pr + 1][1] = q3;
            }
#pragma unroll
            for (int mt = 0; mt < 2; mt++)
#pragma unroll
                for (int nt = 0; nt < 4; nt++) {
                    MMA_B16(c[mt][nt], fah[mt], fbh[nt]);
                    MMA_B16(c[mt][nt], fah[mt], fbl[nt]);
                    MMA_B16(c[mt][nt], fal[mt], fbh[nt]);
                }
        }
    }

#pragma unroll
    for (int mt = 0; mt < 2; mt++) {
        int ro0 = row0 + wm * 32 + mt * 16 + g;
        int ro1 = ro0 + 8;
#pragma unroll
        for (int nt = 0; nt < 4; nt++) {
            int n = col0 + wn * 32 + nt * 8 + 2 * tg;
            float b0 = bias[n], b1 = bias[n + 1];
            float v0 = c[mt][nt][0] + b0, v1 = c[mt][nt][1] + b1;
            float v2 = c[mt][nt][2] + b0, v3 = c[mt][nt][3] + b1;
            if (RELU) {
                v0 = fmaxf(v0, 0.f); v1 = fmaxf(v1, 0.f);
                v2 = fmaxf(v2, 0.f); v3 = fmaxf(v3, 0.f);
            }
            if (WF32) {
                *(float2*)&Cf[(size_t)ro0 * ldc + n] = make_float2(v0, v1);
                *(float2*)&Cf[(size_t)ro1 * ldc + n] = make_float2(v2, v3);
            }
            if (WH16) {
                *(__half2*)&Ch16[(size_t)ro0 * ldc + n] = __floats2half2_rn(v0, v1);
                *(__half2*)&Ch16[(size_t)ro1 * ldc + n] = __floats2half2_rn(v2, v3);
            }
            if (WB16) {
                __nv_bfloat16 h0, h1, h2, h3, l0, l1, l2, l3;
                split1(v0, h0, l0); split1(v1, h1, l1);
                split1(v2, h2, l2); split1(v3, h3, l3);
                *(__nv_bfloat162*)&Chi[(size_t)ro0 * ldc + n] = __nv_bfloat162(h0, h1);
                *(__nv_bfloat162*)&Chi[(size_t)ro1 * ldc + n] = __nv_bfloat162(h2, h3);
                *(__nv_bfloat162*)&Clo[(size_t)ro0 * ldc + n] = __nv_bfloat162(l0, l1);
                *(__nv_bfloat162*)&Clo[(size_t)ro1 * ldc + n] = __nv_bfloat162(l2, l3);
            }
        }
    }
}

// ---------------- tiny GEMM: out[Nx8] = X[Nx64] @ W[8x64]^T + b -------------
__global__ void k_gemm8(const float* __restrict__ X, const float* __restrict__ W,
                        const float* __restrict__ b, float* __restrict__ out) {
    __shared__ float ws[8][64];
    __shared__ float bs[8];
    int t = threadIdx.x;
    for (int i = t; i < 512; i += 256) ws[i >> 6][i & 63] = W[i];
    if (t < 8) bs[t] = b[t];
    __syncthreads();
    int r = blockIdx.x * 256 + t;
    float acc[8];
#pragma unroll
    for (int j = 0; j < 8; j++) acc[j] = bs[j];
    const float* xr = X + (size_t)r * 64;
#pragma unroll
    for (int k = 0; k < 64; k++) {
        float xv = xr[k];
#pragma unroll
        for (int j = 0; j < 8; j++) acc[j] += xv * ws[j][k];
    }
#pragma unroll
    for (int j = 0; j < 8; j++) out[(size_t)r * 8 + j] = acc[j];
}

// ---------------- column mean of ne [N x 128] -> gf [128] -------------------
__global__ void k_zero_gf(float* gf) { gf[threadIdx.x] = 0.f; }

__global__ void k_colsum(const float* __restrict__ ne, float* __restrict__ gf) {
    int col = threadIdx.x;
    int r0 = blockIdx.x * 128;
    float s = 0.f;
    for (int r = 0; r < 128; r++) s += ne[(size_t)(r0 + r) * DOUTC + col];
    atomicAdd(&gf[col], s);
}

__global__ void k_scale_gf(float* gf) { gf[threadIdx.x] *= (1.0f / NN); }

// ---------------- launch ----------------------------------------------------
extern "C" void kernel_launch(void* const* d_in, const int* in_sizes, int n_in,
                              void* d_out, int out_size) {
    const float* X      = (const float*)d_in[0];
    const int*   EIDX   = (const int*)d_in[1];
    const float* enc_w1 = (const float*)d_in[2];
    const float* enc_b1 = (const float*)d_in[3];
    const float* enc_w2 = (const float*)d_in[4];
    const float* enc_b2 = (const float*)d_in[5];
    const float* gin_w  = (const float*)d_in[6];
    const float* gin_b  = (const float*)d_in[7];
    const float* gl_w   = (const float*)d_in[8];
    const float* gl_b   = (const float*)d_in[9];
    const float* gout_w = (const float*)d_in[10];
    const float* gout_b = (const float*)d_in[11];
    const float* proj_w = (const float*)d_in[12];
    const float* proj_b = (const float*)d_in[13];
    const float* hc_w1  = (const float*)d_in[14];
    const float* hc_b1  = (const float*)d_in[15];
    const float* hc_w2  = (const float*)d_in[16];
    const float* hc_b2  = (const float*)d_in[17];

    float* out = (float*)d_out;
    float* ne  = out;                               // [N, 128]
    float* hl  = out + (size_t)NN * DOUTC;          // [N, 8]
    float* gf  = hl + (size_t)NN * 8;               // [128]

    static float* bC = nullptr;
    static void*  bmap = nullptr;
    static __half* xh = nullptr;
    static __nv_bfloat16 *Phi, *Plo, *Qhi, *Qlo, *Whi, *Wlo;
    if (!bC) {
        cudaGetSymbolAddress((void**)&bC, g_bufC);
        cudaGetSymbolAddress(&bmap, g_bitmap);
        cudaGetSymbolAddress((void**)&xh, g_xh);
        cudaGetSymbolAddress((void**)&Phi, g_Phi);
        cudaGetSymbolAddress((void**)&Plo, g_Plo);
        cudaGetSymbolAddress((void**)&Qhi, g_Qhi);
        cudaGetSymbolAddress((void**)&Qlo, g_Qlo);
        cudaGetSymbolAddress((void**)&Whi, g_Whi);
        cudaGetSymbolAddress((void**)&Wlo, g_Wlo);
        cudaFuncSetAttribute(k_gemm_t<1, 0, 1, 0>, cudaFuncAttributeMaxDynamicSharedMemorySize, SMEM_GEMM);
        cudaFuncSetAttribute(k_gemm_t<0, 0, 1, 0>, cudaFuncAttributeMaxDynamicSharedMemorySize, SMEM_GEMM);
        cudaFuncSetAttribute(k_gemm_t<1, 0, 1, 1>, cudaFuncAttributeMaxDynamicSharedMemorySize, SMEM_GEMM);
        cudaFuncSetAttribute(k_gemm_t<1, 1, 1, 0>, cudaFuncAttributeMaxDynamicSharedMemorySize, SMEM_GEMM);
        cudaFuncSetAttribute(k_gemm_t<1, 1, 0, 0>, cudaFuncAttributeMaxDynamicSharedMemorySize, SMEM_GEMM);
    }

    const int EB = EE / 256;                        // 1536

    // setup: splits + init (1 launch), then graph build
    k_split_all<<<3608, 256>>>(X, EIDX, enc_w1, enc_w2, gin_w, gl_w, gout_w,
                               proj_w, hc_w1, Qhi, Qlo, Whi, Wlo);
    cudaMemsetAsync(bmap, 0, ((size_t)NN * NN) / 8);
    k_dedup<<<EB, 256>>>(EIDX);
    k_scan<<<1, 256>>>();
    k_fill<<<EB, 256>>>();

    dim3 g256(NN / BM, 4), g128(NN / BM, 2), g64(NN / BM, 1);

    // node encoder: relu(X@w1)@w2
    k_gemm_t<1, 0, 1, 0><<<g256, 256, SMEM_GEMM>>>(Qhi, Qlo, Whi + OFF_ENC1, Wlo + OFF_ENC1,
                                                   enc_b1, nullptr, Phi, Plo, nullptr, 256, 256);
    k_gemm_t<0, 0, 1, 0><<<g256, 256, SMEM_GEMM>>>(Phi, Plo, Whi + OFF_ENC2, Wlo + OFF_ENC2,
                                                   enc_b2, nullptr, Qhi, Qlo, nullptr, 256, 256);
    // gnn input proj (spmm needs fp16 neighbors + bf16 pair self-term)
    k_gemm_t<1, 0, 1, 1><<<g256, 256, SMEM_GEMM>>>(Qhi, Qlo, Whi + OFF_GIN, Wlo + OFF_GIN,
                                                   gin_b, nullptr, Phi, Plo, xh, 256, 256);
    // 3 message-passing layers
    for (int i = 0; i < 3; i++) {
        k_spmm<<<NN, 256>>>(xh, Phi, Plo, Qhi, Qlo);
        k_gemm_t<1, 0, 1, 1><<<g256, 256, SMEM_GEMM>>>(Qhi, Qlo,
                                                       Whi + OFF_GL + (size_t)i * 65536,
                                                       Wlo + OFF_GL + (size_t)i * 65536,
                                                       gl_b + (size_t)i * HH,
                                                       nullptr, Phi, Plo, xh, 256, 256);
    }
    // gnn output proj (no relu)
    k_gemm_t<0, 0, 1, 0><<<g256, 256, SMEM_GEMM>>>(Phi, Plo, Whi + OFF_GOUT, Wlo + OFF_GOUT,
                                                   gout_b, nullptr, Qhi, Qlo, nullptr, 256, 256);
    // hierarchy proj -> node_embeddings (fp32 out + split for classifier)
    k_gemm_t<1, 1, 1, 0><<<g128, 256, SMEM_GEMM>>>(Qhi, Qlo, Whi + OFF_PROJ, Wlo + OFF_PROJ,
                                                   proj_b, ne, Phi, Plo, nullptr, 256, 128);
    // classifier layer 1 (K=128, M=64, fp32 out only)
    k_gemm_t<1, 1, 0, 0><<<g64, 256, SMEM_GEMM>>>(Phi, Plo, Whi + OFF_HC1, Wlo + OFF_HC1,
                                                  hc_b1, bC, nullptr, nullptr, nullptr, 128, 64);
    k_gemm8<<<NN / 256, 256>>>(bC, hc_w2, hc_b2, hl);
    // global mean
    k_zero_gf<<<1, 128>>>(gf);
    k_colsum<<<NN / 128, 128>>>(ne, gf);
    k_scale_gf<<<1, 128>>>(gf);
}